// round 2
// baseline (speedup 1.0000x reference)
#include <cuda_runtime.h>
#include <math.h>
#include <limits.h>

// Problem constants (buffers sized for this problem; actual n/e taken from in_sizes)
#define NMAX 50000
#define EMAX 800000
#define HCMAX 256

// ---------------- scratch (static __device__, no allocation) ----------------
__device__ float g_hbuf[NMAX * HCMAX];    // GEMM output h  [N,256]
__device__ float g_aggbuf[NMAX * HCMAX];  // aggregated/relu output [N,256]
__device__ float g_h3[NMAX * 2];          // layer3 features [N,2]
__device__ float g_as[NMAX * 4];
__device__ float g_ad[NMAX * 4];
__device__ float g_m[NMAX * 4];
__device__ float g_z[NMAX * 4];
__device__ int   g_mkey[NMAX * 4];
__device__ int   g_deg[NMAX];
__device__ int   g_offs[NMAX];
__device__ int   g_cursor[NMAX];
__device__ int   g_csr_src[EMAX];

// ---------------- small utility kernels ----------------
__global__ void fill_i32(int* p, int v, int n) {
    int i = blockIdx.x * blockDim.x + threadIdx.x;
    if (i < n) p[i] = v;
}
__global__ void fill_f32(float* p, float v, int n) {
    int i = blockIdx.x * blockDim.x + threadIdx.x;
    if (i < n) p[i] = v;
}

// ---------------- CSR build ----------------
__global__ void hist_kernel(const int* __restrict__ ei, int* __restrict__ deg, int E) {
    int i = blockIdx.x * blockDim.x + threadIdx.x;
    if (i < E) atomicAdd(&deg[ei[E + i]], 1);
}

// single-block scan over n ints (exclusive prefix)
__global__ void scan_kernel(const int* __restrict__ deg, int* __restrict__ offs, int n) {
    __shared__ int wsum[32];
    __shared__ int s_carry;
    int lane = threadIdx.x & 31;
    int wid = threadIdx.x >> 5;
    if (threadIdx.x == 0) s_carry = 0;
    __syncthreads();
    for (int base = 0; base < n; base += 1024) {
        int i = base + threadIdx.x;
        int v = (i < n) ? deg[i] : 0;
        int x = v;
#pragma unroll
        for (int o = 1; o < 32; o <<= 1) {
            int t = __shfl_up_sync(0xffffffffu, x, o);
            if (lane >= o) x += t;
        }
        if (lane == 31) wsum[wid] = x;
        __syncthreads();
        if (wid == 0) {
            int y = wsum[lane];
#pragma unroll
            for (int o = 1; o < 32; o <<= 1) {
                int t = __shfl_up_sync(0xffffffffu, y, o);
                if (lane >= o) y += t;
            }
            wsum[lane] = y;
        }
        __syncthreads();
        int carry = s_carry;
        int woff = wid ? wsum[wid - 1] : 0;
        if (i < n) offs[i] = carry + woff + x - v;
        __syncthreads();
        if (threadIdx.x == 0) s_carry = carry + wsum[31];
        __syncthreads();
    }
}

__global__ void scatter_kernel(const int* __restrict__ ei, const int* __restrict__ offs,
                               int* __restrict__ cursor, int* __restrict__ csr_src, int E) {
    int i = blockIdx.x * blockDim.x + threadIdx.x;
    if (i >= E) return;
    int s = ei[i];
    int d = ei[E + i];
    int p = atomicAdd(&cursor[d], 1);
    csr_src[offs[d] + p] = s;
}

// ---------------- SGEMM (fp32, 128x128x8, 8x8 per thread) ----------------
__global__ __launch_bounds__(256) void sgemm_kernel(const float* __restrict__ A,
                                                    const float* __restrict__ B,
                                                    float* __restrict__ C,
                                                    int M, int Nn, int K) {
    const int BM = 128, BN = 128, BK = 8, TM = 8, TN = 8;
    __shared__ float As[BK][BM + 4];
    __shared__ float Bs[BK][BN];
    int bm = blockIdx.x * BM;
    int bn = blockIdx.y * BN;
    int tid = threadIdx.x;
    int tx = tid % 16;
    int ty = tid / 16;
    float acc[TM][TN];
#pragma unroll
    for (int m = 0; m < TM; m++)
#pragma unroll
        for (int nq = 0; nq < TN; nq++) acc[m][nq] = 0.f;

    for (int k0 = 0; k0 < K; k0 += BK) {
#pragma unroll
        for (int l = 0; l < 4; l++) {
            int idx = tid + l * 256;
            int r = idx >> 3, c = idx & 7;
            int gr = bm + r;
            As[c][r] = (gr < M) ? A[(size_t)gr * K + k0 + c] : 0.f;
        }
#pragma unroll
        for (int l = 0; l < 4; l++) {
            int idx = tid + l * 256;
            int r = idx >> 7, c = idx & 127;
            Bs[r][c] = B[(size_t)(k0 + r) * Nn + bn + c];
        }
        __syncthreads();
#pragma unroll
        for (int kk = 0; kk < BK; kk++) {
            float a[TM], b[TN];
#pragma unroll
            for (int m = 0; m < TM; m++) a[m] = As[kk][ty * TM + m];
#pragma unroll
            for (int nq = 0; nq < TN; nq++) b[nq] = Bs[kk][tx * TN + nq];
#pragma unroll
            for (int m = 0; m < TM; m++)
#pragma unroll
                for (int nq = 0; nq < TN; nq++) acc[m][nq] += a[m] * b[nq];
        }
        __syncthreads();
    }
#pragma unroll
    for (int m = 0; m < TM; m++) {
        int gr = bm + ty * TM + m;
        if (gr < M) {
#pragma unroll
            for (int nq = 0; nq < TN; nq++)
                C[(size_t)gr * Nn + bn + tx * TN + nq] = acc[m][nq];
        }
    }
}

// ---------------- per-node attention coefficients ----------------
// H=4, C=64 layers: one warp per node.
__global__ void node_alpha4_kernel(const float* __restrict__ h,
                                   const float* __restrict__ a_s,
                                   const float* __restrict__ a_d,
                                   float* __restrict__ as, float* __restrict__ ad, int n) {
    int gt = blockIdx.x * blockDim.x + threadIdx.x;
    int warp = gt >> 5;
    int lane = gt & 31;
    if (warp >= n) return;
    const float* hr = h + (size_t)warp * 256;
    float ps[4] = {0.f, 0.f, 0.f, 0.f};
    float pd[4] = {0.f, 0.f, 0.f, 0.f};
#pragma unroll
    for (int k = 0; k < 8; k++) {
        int i = lane + 32 * k;
        float v = hr[i];
        ps[k >> 1] += v * a_s[i];
        pd[k >> 1] += v * a_d[i];
    }
#pragma unroll
    for (int hh = 0; hh < 4; hh++) {
        float s = ps[hh], d = pd[hh];
#pragma unroll
        for (int o = 16; o; o >>= 1) {
            s += __shfl_xor_sync(0xffffffffu, s, o);
            d += __shfl_xor_sync(0xffffffffu, d, o);
        }
        if (lane == 0) {
            as[warp * 4 + hh] = s;
            ad[warp * 4 + hh] = d;
        }
    }
}

// layer3: H=1, C=2
__global__ void node_alpha3_kernel(const float* __restrict__ h3,
                                   const float* __restrict__ a_s,
                                   const float* __restrict__ a_d,
                                   float* __restrict__ as, float* __restrict__ ad, int n) {
    int i = blockIdx.x * blockDim.x + threadIdx.x;
    if (i >= n) return;
    float v0 = h3[2 * i], v1 = h3[2 * i + 1];
    as[i] = v0 * a_s[0] + v1 * a_s[1];
    ad[i] = v0 * a_d[0] + v1 * a_d[1];
}

// ---------------- edge softmax (max / sum) ----------------
__device__ __forceinline__ float lrelu(float v) { return v > 0.f ? v : 0.2f * v; }

__global__ void edge_max_kernel(const int* __restrict__ ei, const float* __restrict__ as,
                                const float* __restrict__ ad, int* __restrict__ mkey,
                                int E, int H) {
    int idx = blockIdx.x * blockDim.x + threadIdx.x;
    if (idx >= E * H) return;
    int e = idx / H, hh = idx - e * H;
    int s = ei[e], d = ei[E + e];
    float v = lrelu(as[s * H + hh] + ad[d * H + hh]);
    int b = __float_as_int(v);
    int key = (b >= 0) ? b : (b ^ 0x7fffffff);
    atomicMax(&mkey[d * H + hh], key);
}

__global__ void decode_m_kernel(const int* __restrict__ mkey, float* __restrict__ m, int n) {
    int i = blockIdx.x * blockDim.x + threadIdx.x;
    if (i >= n) return;
    int k = mkey[i];
    float v;
    if (k == INT_MIN) v = 0.f;  // node with no incoming edges: value never used
    else {
        int b = (k >= 0) ? k : (k ^ 0x7fffffff);
        v = __int_as_float(b);
    }
    m[i] = v;
}

__global__ void edge_sum_kernel(const int* __restrict__ ei, const float* __restrict__ as,
                                const float* __restrict__ ad, const float* __restrict__ m,
                                float* __restrict__ z, int E, int H) {
    int idx = blockIdx.x * blockDim.x + threadIdx.x;
    if (idx >= E * H) return;
    int e = idx / H, hh = idx - e * H;
    int s = ei[e], d = ei[E + e];
    float v = lrelu(as[s * H + hh] + ad[d * H + hh]);
    float p = __expf(v - m[d * H + hh]);
    atomicAdd(&z[d * H + hh], p);
}

// ---------------- CSR aggregation (H=4, C=64; one block per dst node) ----------------
__global__ __launch_bounds__(256) void agg_kernel(const float* __restrict__ h,
                                                  const int* __restrict__ csr_src,
                                                  const int* __restrict__ offs,
                                                  const int* __restrict__ deg,
                                                  const float* __restrict__ as,
                                                  const float* __restrict__ ad,
                                                  const float* __restrict__ m,
                                                  const float* __restrict__ z,
                                                  const float* __restrict__ bias,
                                                  float* __restrict__ out, int do_relu) {
    int n = blockIdx.x;
    int t = threadIdx.x;       // channel 0..255
    int head = t >> 6;
    int j = t & 63;
    int st = offs[n], d = deg[n];
    __shared__ float s_alpha[4 * 64];
    __shared__ int s_src[64];
    float adn = ad[n * 4 + head];
    float mn = m[n * 4 + head];
    float zn = z[n * 4 + head] + 1e-16f;
    float acc = 0.f;
    for (int base = 0; base < d; base += 64) {
        int cnt = min(64, d - base);
        __syncthreads();
        if (t < cnt) s_src[t] = csr_src[st + base + t];
        __syncthreads();
        if (j < cnt) {
            int s = s_src[j];
            float e = lrelu(as[s * 4 + head] + adn);
            s_alpha[head * 64 + j] = __expf(e - mn) / zn;
        }
        __syncthreads();
        for (int q = 0; q < cnt; q++) {
            acc += s_alpha[head * 64 + q] * h[(size_t)s_src[q] * 256 + t];
        }
    }
    float v = acc + bias[t];
    if (do_relu) v = v > 0.f ? v : 0.f;
    out[(size_t)n * 256 + t] = v;
}

// layer3 aggregation: one thread per dst node (C=2, H=1)
__global__ void agg3_kernel(const float* __restrict__ h3, const int* __restrict__ csr_src,
                            const int* __restrict__ offs, const int* __restrict__ deg,
                            const float* __restrict__ as, const float* __restrict__ ad,
                            const float* __restrict__ m, const float* __restrict__ z,
                            const float* __restrict__ bias, float* __restrict__ out, int n) {
    int i = blockIdx.x * blockDim.x + threadIdx.x;
    if (i >= n) return;
    int st = offs[i], d = deg[i];
    float adn = ad[i], mn = m[i];
    float zn = z[i] + 1e-16f;
    float a0 = 0.f, a1 = 0.f;
    for (int k = 0; k < d; k++) {
        int s = csr_src[st + k];
        float e = lrelu(as[s] + adn);
        float al = __expf(e - mn) / zn;
        a0 += al * h3[2 * s];
        a1 += al * h3[2 * s + 1];
    }
    out[2 * i] = a0 + bias[0];
    out[2 * i + 1] = a1 + bias[1];
}

// layer3 GEMM: h[N,256] @ W3[256,2] — one warp per node
__global__ void gemm3_kernel(const float* __restrict__ h, const float* __restrict__ W3,
                             float* __restrict__ h3, int n) {
    __shared__ float w[512];
    for (int i = threadIdx.x; i < 512; i += blockDim.x) w[i] = W3[i];
    __syncthreads();
    int gt = blockIdx.x * blockDim.x + threadIdx.x;
    int warp = gt >> 5;
    int lane = gt & 31;
    if (warp >= n) return;
    const float* hr = h + (size_t)warp * 256;
    float a0 = 0.f, a1 = 0.f;
#pragma unroll
    for (int k = 0; k < 8; k++) {
        int i = lane + 32 * k;
        float v = hr[i];
        a0 += v * w[i * 2];
        a1 += v * w[i * 2 + 1];
    }
#pragma unroll
    for (int o = 16; o; o >>= 1) {
        a0 += __shfl_xor_sync(0xffffffffu, a0, o);
        a1 += __shfl_xor_sync(0xffffffffu, a1, o);
    }
    if (lane == 0) {
        h3[2 * warp] = a0;
        h3[2 * warp + 1] = a1;
    }
}

// ---------------- launcher ----------------
static inline int cdiv(int a, int b) { return (a + b - 1) / b; }

extern "C" void kernel_launch(void* const* d_in, const int* in_sizes, int n_in,
                              void* d_out, int out_size) {
    const float* x   = (const float*)d_in[0];
    const int*   ei  = (const int*)d_in[1];
    const float* W1  = (const float*)d_in[2];
    const float* as1 = (const float*)d_in[3];
    const float* ad1 = (const float*)d_in[4];
    const float* b1  = (const float*)d_in[5];
    const float* W2  = (const float*)d_in[6];
    const float* as2 = (const float*)d_in[7];
    const float* ad2 = (const float*)d_in[8];
    const float* b2  = (const float*)d_in[9];
    const float* W3  = (const float*)d_in[10];
    const float* as3 = (const float*)d_in[11];
    const float* ad3 = (const float*)d_in[12];
    const float* b3  = (const float*)d_in[13];
    float* outp = (float*)d_out;

    int n = in_sizes[0] / 128;
    int E = in_sizes[1] / 2;

    float *hbuf, *aggbuf, *h3, *as, *ad, *m, *z;
    int *mkey, *deg, *offs, *cursor, *csr_src;
    cudaGetSymbolAddress((void**)&hbuf, g_hbuf);
    cudaGetSymbolAddress((void**)&aggbuf, g_aggbuf);
    cudaGetSymbolAddress((void**)&h3, g_h3);
    cudaGetSymbolAddress((void**)&as, g_as);
    cudaGetSymbolAddress((void**)&ad, g_ad);
    cudaGetSymbolAddress((void**)&m, g_m);
    cudaGetSymbolAddress((void**)&z, g_z);
    cudaGetSymbolAddress((void**)&mkey, g_mkey);
    cudaGetSymbolAddress((void**)&deg, g_deg);
    cudaGetSymbolAddress((void**)&offs, g_offs);
    cudaGetSymbolAddress((void**)&cursor, g_cursor);
    cudaGetSymbolAddress((void**)&csr_src, g_csr_src);

    // ---- CSR build (graph is the same for all layers) ----
    fill_i32<<<cdiv(n, 256), 256>>>(deg, 0, n);
    fill_i32<<<cdiv(n, 256), 256>>>(cursor, 0, n);
    hist_kernel<<<cdiv(E, 256), 256>>>(ei, deg, E);
    scan_kernel<<<1, 1024>>>(deg, offs, n);
    scatter_kernel<<<cdiv(E, 256), 256>>>(ei, offs, cursor, csr_src, E);

    dim3 gemm_grid(cdiv(n, 128), 2);

    // ---- Layer 1: x[N,128] @ W1[128,256] ----
    sgemm_kernel<<<gemm_grid, 256>>>(x, W1, hbuf, n, 256, 128);
    node_alpha4_kernel<<<cdiv(n * 32, 256), 256>>>(hbuf, as1, ad1, as, ad, n);
    fill_i32<<<cdiv(n * 4, 256), 256>>>(mkey, INT_MIN, n * 4);
    fill_f32<<<cdiv(n * 4, 256), 256>>>(z, 0.f, n * 4);
    edge_max_kernel<<<cdiv(E * 4, 256), 256>>>(ei, as, ad, mkey, E, 4);
    decode_m_kernel<<<cdiv(n * 4, 256), 256>>>(mkey, m, n * 4);
    edge_sum_kernel<<<cdiv(E * 4, 256), 256>>>(ei, as, ad, m, z, E, 4);
    agg_kernel<<<n, 256>>>(hbuf, csr_src, offs, deg, as, ad, m, z, b1, aggbuf, 1);

    // ---- Layer 2: relu(h1)[N,256] @ W2[256,256] ----
    sgemm_kernel<<<gemm_grid, 256>>>(aggbuf, W2, hbuf, n, 256, 256);
    node_alpha4_kernel<<<cdiv(n * 32, 256), 256>>>(hbuf, as2, ad2, as, ad, n);
    fill_i32<<<cdiv(n * 4, 256), 256>>>(mkey, INT_MIN, n * 4);
    fill_f32<<<cdiv(n * 4, 256), 256>>>(z, 0.f, n * 4);
    edge_max_kernel<<<cdiv(E * 4, 256), 256>>>(ei, as, ad, mkey, E, 4);
    decode_m_kernel<<<cdiv(n * 4, 256), 256>>>(mkey, m, n * 4);
    edge_sum_kernel<<<cdiv(E * 4, 256), 256>>>(ei, as, ad, m, z, E, 4);
    agg_kernel<<<n, 256>>>(hbuf, csr_src, offs, deg, as, ad, m, z, b2, aggbuf, 1);

    // ---- Layer 3: relu(h2)[N,256] @ W3[256,2], H=1, C=2 ----
    gemm3_kernel<<<cdiv(n * 32, 256), 256>>>(aggbuf, W3, h3, n);
    node_alpha3_kernel<<<cdiv(n, 256), 256>>>(h3, as3, ad3, as, ad, n);
    fill_i32<<<cdiv(n, 256), 256>>>(mkey, INT_MIN, n);
    fill_f32<<<cdiv(n, 256), 256>>>(z, 0.f, n);
    edge_max_kernel<<<cdiv(E, 256), 256>>>(ei, as, ad, mkey, E, 1);
    decode_m_kernel<<<cdiv(n, 256), 256>>>(mkey, m, n);
    edge_sum_kernel<<<cdiv(E, 256), 256>>>(ei, as, ad, m, z, E, 1);
    agg3_kernel<<<cdiv(n, 256), 256>>>(h3, csr_src, offs, deg, as, ad, m, z, b3, outp, n);
}

// round 3
// speedup vs baseline: 1.4550x; 1.4550x over previous
#include <cuda_runtime.h>
#include <math.h>
#include <limits.h>

#define NMAX 50000
#define EMAX 800000
#define HCMAX 256

// ---------------- scratch ----------------
__device__ float g_hbuf[NMAX * HCMAX];
__device__ float g_aggbuf[NMAX * HCMAX];
__device__ float g_h3[NMAX * 2];
__device__ float g_as[NMAX * 4];
__device__ float g_ad[NMAX * 4];
__device__ int   g_deg[NMAX];
__device__ int   g_offs[NMAX];
__device__ int   g_cursor[NMAX];
__device__ int   g_bsum[256];
__device__ int   g_csr_src[EMAX];

static inline int cdiv(int a, int b) { return (a + b - 1) / b; }

// ---------------- utility ----------------
__global__ void fill_i32(int* p, int v, int n) {
    int i = blockIdx.x * blockDim.x + threadIdx.x;
    if (i < n) p[i] = v;
}

// ---------------- CSR build ----------------
__global__ void hist_kernel(const int* __restrict__ ei, int* __restrict__ deg, int E) {
    int i = blockIdx.x * blockDim.x + threadIdx.x;
    if (i < E) atomicAdd(&deg[ei[E + i]], 1);
}

// per-block exclusive scan of 256 elems + block total
__global__ void scan_block_kernel(const int* __restrict__ deg, int* __restrict__ offs,
                                  int* __restrict__ bsum, int n) {
    __shared__ int ws[8];
    int t = threadIdx.x, lane = t & 31, w = t >> 5;
    int i = blockIdx.x * 256 + t;
    int v = (i < n) ? deg[i] : 0;
    int x = v;
#pragma unroll
    for (int o = 1; o < 32; o <<= 1) {
        int tv = __shfl_up_sync(0xffffffffu, x, o);
        if (lane >= o) x += tv;
    }
    if (lane == 31) ws[w] = x;
    __syncthreads();
    if (w == 0) {
        int y = (lane < 8) ? ws[lane] : 0;
#pragma unroll
        for (int o = 1; o < 8; o <<= 1) {
            int tv = __shfl_up_sync(0xffffffffu, y, o);
            if (lane >= o) y += tv;
        }
        if (lane < 8) ws[lane] = y;
    }
    __syncthreads();
    int woff = w ? ws[w - 1] : 0;
    if (i < n) offs[i] = woff + x - v;
    if (t == 255) bsum[blockIdx.x] = ws[7];
}

// single-block exclusive scan of block sums (nb <= 256)
__global__ void scan_sums_kernel(int* bsum, int nb) {
    __shared__ int ws[8];
    int t = threadIdx.x, lane = t & 31, w = t >> 5;
    int v = (t < nb) ? bsum[t] : 0;
    int x = v;
#pragma unroll
    for (int o = 1; o < 32; o <<= 1) {
        int tv = __shfl_up_sync(0xffffffffu, x, o);
        if (lane >= o) x += tv;
    }
    if (lane == 31) ws[w] = x;
    __syncthreads();
    if (w == 0) {
        int y = (lane < 8) ? ws[lane] : 0;
#pragma unroll
        for (int o = 1; o < 8; o <<= 1) {
            int tv = __shfl_up_sync(0xffffffffu, y, o);
            if (lane >= o) y += tv;
        }
        if (lane < 8) ws[lane] = y;
    }
    __syncthreads();
    int woff = w ? ws[w - 1] : 0;
    if (t < nb) bsum[t] = woff + x - v;
}

__global__ void scan_add_kernel(int* __restrict__ offs, int* __restrict__ cursor,
                                const int* __restrict__ bsum, int n) {
    int i = blockIdx.x * blockDim.x + threadIdx.x;
    if (i < n) {
        int o = offs[i] + bsum[blockIdx.x];
        offs[i] = o;
        cursor[i] = o;
    }
}

__global__ void scatter_kernel(const int* __restrict__ ei, int* __restrict__ cursor,
                               int* __restrict__ csr_src, int E) {
    int i = blockIdx.x * blockDim.x + threadIdx.x;
    if (i >= E) return;
    int s = ei[i];
    int d = ei[E + i];
    int p = atomicAdd(&cursor[d], 1);
    csr_src[p] = s;
}

// ---------------- tf32 tensor-core GEMM: C[M,256] = A[M,K] @ B[K,256] ----------------
__device__ __forceinline__ unsigned f2tf(float x) {
    unsigned u;
    asm("cvt.rna.tf32.f32 %0, %1;" : "=r"(u) : "f"(x));
    return u;
}

__device__ __forceinline__ void mma_tf32(float* c, const unsigned* a, unsigned b0, unsigned b1) {
    asm volatile(
        "mma.sync.aligned.m16n8k8.row.col.f32.tf32.tf32.f32 "
        "{%0,%1,%2,%3},{%4,%5,%6,%7},{%8,%9},{%0,%1,%2,%3};"
        : "+f"(c[0]), "+f"(c[1]), "+f"(c[2]), "+f"(c[3])
        : "r"(a[0]), "r"(a[1]), "r"(a[2]), "r"(a[3]), "r"(b0), "r"(b1));
}

#define GBM 128
#define GBN 128
#define GBK 32

__global__ __launch_bounds__(256) void mma_gemm_kernel(const float* __restrict__ A,
                                                       const float* __restrict__ B,
                                                       float* __restrict__ C,
                                                       int M, int K) {
    __shared__ unsigned As[GBM][GBK + 4];  // [row][k]
    __shared__ unsigned Bs[GBK][GBN + 4];  // [k][col]
    int tid = threadIdx.x;
    int bm = blockIdx.x * GBM, bn = blockIdx.y * GBN;
    int lane = tid & 31, wid = tid >> 5;
    int wm = wid >> 1, wn = wid & 1;  // warp tile (wm*32, wn*64)
    int g = lane >> 2, l4 = lane & 3;

    float acc[2][8][4];
#pragma unroll
    for (int mt = 0; mt < 2; mt++)
#pragma unroll
        for (int nt = 0; nt < 8; nt++)
#pragma unroll
            for (int c = 0; c < 4; c++) acc[mt][nt][c] = 0.f;

    float4 ra[4], rb[4];
    int T = K / GBK;

    // stage 0 load
#pragma unroll
    for (int i = 0; i < 4; i++) {
        int idx = tid + i * 256;
        int row = idx >> 3, kq = idx & 7;
        int gr = bm + row;
        ra[i] = (gr < M) ? *(const float4*)&A[(size_t)gr * K + kq * 4]
                         : make_float4(0.f, 0.f, 0.f, 0.f);
        int r = idx >> 5, c4 = idx & 31;
        rb[i] = *(const float4*)&B[(size_t)r * 256 + bn + c4 * 4];
    }

    for (int t = 0; t < T; t++) {
        // store staged regs (cvt to tf32)
#pragma unroll
        for (int i = 0; i < 4; i++) {
            int idx = tid + i * 256;
            int row = idx >> 3, kq = idx & 7;
            uint4 av = make_uint4(f2tf(ra[i].x), f2tf(ra[i].y), f2tf(ra[i].z), f2tf(ra[i].w));
            *(uint4*)&As[row][kq * 4] = av;
            int r = idx >> 5, c4 = idx & 31;
            uint4 bv = make_uint4(f2tf(rb[i].x), f2tf(rb[i].y), f2tf(rb[i].z), f2tf(rb[i].w));
            *(uint4*)&Bs[r][c4 * 4] = bv;
        }
        __syncthreads();

        // prefetch next tile into regs
        if (t + 1 < T) {
            int k0 = (t + 1) * GBK;
#pragma unroll
            for (int i = 0; i < 4; i++) {
                int idx = tid + i * 256;
                int row = idx >> 3, kq = idx & 7;
                int gr = bm + row;
                ra[i] = (gr < M) ? *(const float4*)&A[(size_t)gr * K + k0 + kq * 4]
                                 : make_float4(0.f, 0.f, 0.f, 0.f);
                int r = idx >> 5, c4 = idx & 31;
                rb[i] = *(const float4*)&B[(size_t)(k0 + r) * 256 + bn + c4 * 4];
            }
        }

        // compute GBK=32 (4 k-steps of 8)
#pragma unroll
        for (int ks = 0; ks < 4; ks++) {
            int kb = ks * 8;
            unsigned a[2][4];
#pragma unroll
            for (int mt = 0; mt < 2; mt++) {
                int row = wm * 32 + mt * 16 + g;
                a[mt][0] = As[row][kb + l4];
                a[mt][1] = As[row + 8][kb + l4];
                a[mt][2] = As[row][kb + l4 + 4];
                a[mt][3] = As[row + 8][kb + l4 + 4];
            }
#pragma unroll
            for (int nt = 0; nt < 8; nt++) {
                int col = wn * 64 + nt * 8 + g;
                unsigned b0 = Bs[kb + l4][col];
                unsigned b1 = Bs[kb + l4 + 4][col];
                mma_tf32(acc[0][nt], a[0], b0, b1);
                mma_tf32(acc[1][nt], a[1], b0, b1);
            }
        }
        __syncthreads();
    }

    // epilogue
#pragma unroll
    for (int mt = 0; mt < 2; mt++) {
#pragma unroll
        for (int nt = 0; nt < 8; nt++) {
            int row0 = bm + wm * 32 + mt * 16 + g;
            int col = bn + wn * 64 + nt * 8 + l4 * 2;
            if (row0 < M)
                *(float2*)&C[(size_t)row0 * 256 + col] = make_float2(acc[mt][nt][0], acc[mt][nt][1]);
            if (row0 + 8 < M)
                *(float2*)&C[(size_t)(row0 + 8) * 256 + col] = make_float2(acc[mt][nt][2], acc[mt][nt][3]);
        }
    }
}

// ---------------- per-node attention coefficients (H=4, C=64) ----------------
__global__ void node_alpha4_kernel(const float* __restrict__ h,
                                   const float* __restrict__ a_s,
                                   const float* __restrict__ a_d,
                                   float* __restrict__ as, float* __restrict__ ad, int n) {
    int gt = blockIdx.x * blockDim.x + threadIdx.x;
    int warp = gt >> 5;
    int lane = gt & 31;
    if (warp >= n) return;
    const float* hr = h + (size_t)warp * 256;
    float ps[4] = {0.f, 0.f, 0.f, 0.f};
    float pd[4] = {0.f, 0.f, 0.f, 0.f};
#pragma unroll
    for (int k = 0; k < 8; k++) {
        int i = lane + 32 * k;
        float v = hr[i];
        ps[k >> 1] += v * a_s[i];
        pd[k >> 1] += v * a_d[i];
    }
#pragma unroll
    for (int hh = 0; hh < 4; hh++) {
        float s = ps[hh], d = pd[hh];
#pragma unroll
        for (int o = 16; o; o >>= 1) {
            s += __shfl_xor_sync(0xffffffffu, s, o);
            d += __shfl_xor_sync(0xffffffffu, d, o);
        }
        if (lane == 0) {
            as[warp * 4 + hh] = s;
            ad[warp * 4 + hh] = d;
        }
    }
}

__device__ __forceinline__ float lrelu(float v) { return v > 0.f ? v : 0.2f * v; }

// ---------------- fused aggregation + online softmax (H=4, C=64) ----------------
__global__ __launch_bounds__(256) void agg_fused_kernel(const float* __restrict__ h,
                                                        const int* __restrict__ csr_src,
                                                        const int* __restrict__ offs,
                                                        const int* __restrict__ deg,
                                                        const float* __restrict__ as,
                                                        const float* __restrict__ ad,
                                                        const float* __restrict__ bias,
                                                        float* __restrict__ out, int do_relu) {
    int n = blockIdx.x;
    int t = threadIdx.x;
    int head = t >> 6, j = t & 63;
    int lane = t & 31, w = t >> 5;
    int st = offs[n], d = deg[n];
    __shared__ int s_src[64];
    __shared__ float s_alpha[256];
    __shared__ float s_mz[16];
    float adn = ad[n * 4 + head];

    // pass 1: online softmax stats
    float mt = -1e30f, zt = 0.f;
    for (int base = 0; base < d; base += 64) {
        int cnt = min(64, d - base);
        __syncthreads();
        if (t < cnt) s_src[t] = csr_src[st + base + t];
        __syncthreads();
        if (j < cnt) {
            int s = s_src[j];
            float e = lrelu(as[s * 4 + head] + adn);
            float nm = fmaxf(mt, e);
            zt = zt * __expf(mt - nm) + __expf(e - nm);
            mt = nm;
        }
    }
#pragma unroll
    for (int o = 16; o; o >>= 1) {
        float om = __shfl_xor_sync(0xffffffffu, mt, o);
        float oz = __shfl_xor_sync(0xffffffffu, zt, o);
        float nm = fmaxf(mt, om);
        zt = zt * __expf(mt - nm) + oz * __expf(om - nm);
        mt = nm;
    }
    if (lane == 0) { s_mz[w] = mt; s_mz[8 + w] = zt; }
    __syncthreads();
    float mh, rzh;
    {
        float m0 = s_mz[head * 2], m1 = s_mz[head * 2 + 1];
        float z0 = s_mz[8 + head * 2], z1 = s_mz[8 + head * 2 + 1];
        float nm = fmaxf(m0, m1);
        float z = z0 * __expf(m0 - nm) + z1 * __expf(m1 - nm);
        mh = nm;
        rzh = 1.f / (z + 1e-16f);
    }

    // pass 2: aggregate
    float acc = 0.f;
    for (int base = 0; base < d; base += 64) {
        int cnt = min(64, d - base);
        __syncthreads();
        if (t < cnt) s_src[t] = csr_src[st + base + t];
        __syncthreads();
        if (j < cnt) {
            int s = s_src[j];
            float e = lrelu(as[s * 4 + head] + adn);
            s_alpha[head * 64 + j] = __expf(e - mh) * rzh;
        }
        __syncthreads();
#pragma unroll 4
        for (int q = 0; q < cnt; q++)
            acc += s_alpha[head * 64 + q] * h[(size_t)s_src[q] * 256 + t];
    }
    float v = acc + bias[t];
    if (do_relu) v = fmaxf(v, 0.f);
    out[(size_t)n * 256 + t] = v;
}

// ---------------- layer3: GEMM [N,256]@[256,2] fused with alpha coeffs ----------------
__global__ void gemm3_alpha_kernel(const float* __restrict__ h, const float* __restrict__ W3,
                                   const float* __restrict__ a_s, const float* __restrict__ a_d,
                                   float* __restrict__ h3, float* __restrict__ as,
                                   float* __restrict__ ad, int n) {
    __shared__ float w[512];
    for (int i = threadIdx.x; i < 512; i += blockDim.x) w[i] = W3[i];
    __syncthreads();
    int gt = blockIdx.x * blockDim.x + threadIdx.x;
    int warp = gt >> 5;
    int lane = gt & 31;
    if (warp >= n) return;
    const float* hr = h + (size_t)warp * 256;
    float a0 = 0.f, a1 = 0.f;
#pragma unroll
    for (int k = 0; k < 8; k++) {
        int i = lane + 32 * k;
        float v = hr[i];
        a0 += v * w[i * 2];
        a1 += v * w[i * 2 + 1];
    }
#pragma unroll
    for (int o = 16; o; o >>= 1) {
        a0 += __shfl_xor_sync(0xffffffffu, a0, o);
        a1 += __shfl_xor_sync(0xffffffffu, a1, o);
    }
    if (lane == 0) {
        h3[2 * warp] = a0;
        h3[2 * warp + 1] = a1;
        as[warp] = a0 * a_s[0] + a1 * a_s[1];
        ad[warp] = a0 * a_d[0] + a1 * a_d[1];
    }
}

// ---------------- layer3 fused aggregation (H=1, C=2) ----------------
__global__ void agg3_fused_kernel(const float* __restrict__ h3, const int* __restrict__ csr_src,
                                  const int* __restrict__ offs, const int* __restrict__ deg,
                                  const float* __restrict__ as, const float* __restrict__ ad,
                                  const float* __restrict__ bias, float* __restrict__ out, int n) {
    int i = blockIdx.x * blockDim.x + threadIdx.x;
    if (i >= n) return;
    int st = offs[i], d = deg[i];
    float adn = ad[i];
    float mt = -1e30f, zt = 0.f;
    for (int k = 0; k < d; k++) {
        int s = csr_src[st + k];
        float e = lrelu(as[s] + adn);
        float nm = fmaxf(mt, e);
        zt = zt * __expf(mt - nm) + __expf(e - nm);
        mt = nm;
    }
    float rz = 1.f / (zt + 1e-16f);
    float a0 = 0.f, a1 = 0.f;
    for (int k = 0; k < d; k++) {
        int s = csr_src[st + k];
        float e = lrelu(as[s] + adn);
        float al = __expf(e - mt) * rz;
        a0 += al * h3[2 * s];
        a1 += al * h3[2 * s + 1];
    }
    out[2 * i] = a0 + bias[0];
    out[2 * i + 1] = a1 + bias[1];
}

// ---------------- launcher ----------------
extern "C" void kernel_launch(void* const* d_in, const int* in_sizes, int n_in,
                              void* d_out, int out_size) {
    const float* x   = (const float*)d_in[0];
    const int*   ei  = (const int*)d_in[1];
    const float* W1  = (const float*)d_in[2];
    const float* as1 = (const float*)d_in[3];
    const float* ad1 = (const float*)d_in[4];
    const float* b1  = (const float*)d_in[5];
    const float* W2  = (const float*)d_in[6];
    const float* as2 = (const float*)d_in[7];
    const float* ad2 = (const float*)d_in[8];
    const float* b2  = (const float*)d_in[9];
    const float* W3  = (const float*)d_in[10];
    const float* as3 = (const float*)d_in[11];
    const float* ad3 = (const float*)d_in[12];
    const float* b3  = (const float*)d_in[13];
    float* outp = (float*)d_out;

    int n = in_sizes[0] / 128;
    int E = in_sizes[1] / 2;

    float *hbuf, *aggbuf, *h3, *as, *ad;
    int *deg, *offs, *cursor, *bsum, *csr_src;
    cudaGetSymbolAddress((void**)&hbuf, g_hbuf);
    cudaGetSymbolAddress((void**)&aggbuf, g_aggbuf);
    cudaGetSymbolAddress((void**)&h3, g_h3);
    cudaGetSymbolAddress((void**)&as, g_as);
    cudaGetSymbolAddress((void**)&ad, g_ad);
    cudaGetSymbolAddress((void**)&deg, g_deg);
    cudaGetSymbolAddress((void**)&offs, g_offs);
    cudaGetSymbolAddress((void**)&cursor, g_cursor);
    cudaGetSymbolAddress((void**)&bsum, g_bsum);
    cudaGetSymbolAddress((void**)&csr_src, g_csr_src);

    int nb = cdiv(n, 256);

    // ---- CSR build ----
    fill_i32<<<cdiv(n, 256), 256>>>(deg, 0, n);
    hist_kernel<<<cdiv(E, 256), 256>>>(ei, deg, E);
    scan_block_kernel<<<nb, 256>>>(deg, offs, bsum, n);
    scan_sums_kernel<<<1, 256>>>(bsum, nb);
    scan_add_kernel<<<nb, 256>>>(offs, cursor, bsum, n);
    scatter_kernel<<<cdiv(E, 256), 256>>>(ei, cursor, csr_src, E);

    dim3 gemm_grid(cdiv(n, 128), 2);

    // ---- Layer 1 ----
    mma_gemm_kernel<<<gemm_grid, 256>>>(x, W1, hbuf, n, 128);
    node_alpha4_kernel<<<cdiv(n * 32, 256), 256>>>(hbuf, as1, ad1, as, ad, n);
    agg_fused_kernel<<<n, 256>>>(hbuf, csr_src, offs, deg, as, ad, b1, aggbuf, 1);

    // ---- Layer 2 ----
    mma_gemm_kernel<<<gemm_grid, 256>>>(aggbuf, W2, hbuf, n, 256);
    node_alpha4_kernel<<<cdiv(n * 32, 256), 256>>>(hbuf, as2, ad2, as, ad, n);
    agg_fused_kernel<<<n, 256>>>(hbuf, csr_src, offs, deg, as, ad, b2, aggbuf, 1);

    // ---- Layer 3 ----
    gemm3_alpha_kernel<<<cdiv(n * 32, 256), 256>>>(aggbuf, W3, as3, ad3, h3, as, ad, n);
    agg3_fused_kernel<<<cdiv(n, 256), 256>>>(h3, csr_src, offs, deg, as, ad, b3, outp, n);
}

// round 4
// speedup vs baseline: 1.9999x; 1.3745x over previous
#include <cuda_runtime.h>
#include <math.h>
#include <limits.h>

#define NMAX 50000
#define EMAX 800000
#define HCMAX 256

// ---------------- scratch ----------------
__device__ float g_hbuf[NMAX * HCMAX];
__device__ float g_aggbuf[NMAX * HCMAX];
__device__ float g_h3[NMAX * 2];
__device__ float g_as[NMAX * 4];
__device__ float g_ad[NMAX * 4];
__device__ int   g_deg[NMAX];
__device__ int   g_offs[NMAX];
__device__ int   g_cursor[NMAX];
__device__ int   g_bsum[256];
__device__ int   g_csr_src[EMAX];

static inline int cdiv(int a, int b) { return (a + b - 1) / b; }

// ---------------- utility ----------------
__global__ void fill_i32(int* p, int v, int n) {
    int i = blockIdx.x * blockDim.x + threadIdx.x;
    if (i < n) p[i] = v;
}

// ---------------- CSR build ----------------
__global__ void hist_kernel(const int* __restrict__ ei, int* __restrict__ deg, int E) {
    int i = blockIdx.x * blockDim.x + threadIdx.x;
    if (i < E) atomicAdd(&deg[ei[E + i]], 1);
}

__global__ void scan_block_kernel(const int* __restrict__ deg, int* __restrict__ offs,
                                  int* __restrict__ bsum, int n) {
    __shared__ int ws[8];
    int t = threadIdx.x, lane = t & 31, w = t >> 5;
    int i = blockIdx.x * 256 + t;
    int v = (i < n) ? deg[i] : 0;
    int x = v;
#pragma unroll
    for (int o = 1; o < 32; o <<= 1) {
        int tv = __shfl_up_sync(0xffffffffu, x, o);
        if (lane >= o) x += tv;
    }
    if (lane == 31) ws[w] = x;
    __syncthreads();
    if (w == 0) {
        int y = (lane < 8) ? ws[lane] : 0;
#pragma unroll
        for (int o = 1; o < 8; o <<= 1) {
            int tv = __shfl_up_sync(0xffffffffu, y, o);
            if (lane >= o) y += tv;
        }
        if (lane < 8) ws[lane] = y;
    }
    __syncthreads();
    int woff = w ? ws[w - 1] : 0;
    if (i < n) offs[i] = woff + x - v;
    if (t == 255) bsum[blockIdx.x] = ws[7];
}

__global__ void scan_sums_kernel(int* bsum, int nb) {
    __shared__ int ws[8];
    int t = threadIdx.x, lane = t & 31, w = t >> 5;
    int v = (t < nb) ? bsum[t] : 0;
    int x = v;
#pragma unroll
    for (int o = 1; o < 32; o <<= 1) {
        int tv = __shfl_up_sync(0xffffffffu, x, o);
        if (lane >= o) x += tv;
    }
    if (lane == 31) ws[w] = x;
    __syncthreads();
    if (w == 0) {
        int y = (lane < 8) ? ws[lane] : 0;
#pragma unroll
        for (int o = 1; o < 8; o <<= 1) {
            int tv = __shfl_up_sync(0xffffffffu, y, o);
            if (lane >= o) y += tv;
        }
        if (lane < 8) ws[lane] = y;
    }
    __syncthreads();
    int woff = w ? ws[w - 1] : 0;
    if (t < nb) bsum[t] = woff + x - v;
}

__global__ void scan_add_kernel(int* __restrict__ offs, int* __restrict__ cursor,
                                const int* __restrict__ bsum, int n) {
    int i = blockIdx.x * blockDim.x + threadIdx.x;
    if (i < n) {
        int o = offs[i] + bsum[blockIdx.x];
        offs[i] = o;
        cursor[i] = o;
    }
}

__global__ void scatter_kernel(const int* __restrict__ ei, int* __restrict__ cursor,
                               int* __restrict__ csr_src, int E) {
    int i = blockIdx.x * blockDim.x + threadIdx.x;
    if (i >= E) return;
    int s = ei[i];
    int d = ei[E + i];
    int p = atomicAdd(&cursor[d], 1);
    csr_src[p] = s;
}

// ---------------- tf32 tensor-core GEMM: C[M,256] = A[M,K] @ B[K,256] ----------------
__device__ __forceinline__ unsigned f2tf(float x) {
    unsigned u;
    asm("cvt.rna.tf32.f32 %0, %1;" : "=r"(u) : "f"(x));
    return u;
}

__device__ __forceinline__ void mma_tf32(float* c, const unsigned* a, unsigned b0, unsigned b1) {
    asm volatile(
        "mma.sync.aligned.m16n8k8.row.col.f32.tf32.tf32.f32 "
        "{%0,%1,%2,%3},{%4,%5,%6,%7},{%8,%9},{%0,%1,%2,%3};"
        : "+f"(c[0]), "+f"(c[1]), "+f"(c[2]), "+f"(c[3])
        : "r"(a[0]), "r"(a[1]), "r"(a[2]), "r"(a[3]), "r"(b0), "r"(b1));
}

#define GBM 128
#define GBN 128
#define GBK 32

__global__ __launch_bounds__(256) void mma_gemm_kernel(const float* __restrict__ A,
                                                       const float* __restrict__ B,
                                                       float* __restrict__ C,
                                                       int M, int K) {
    __shared__ unsigned As[GBM][GBK + 4];
    __shared__ unsigned Bs[GBK][GBN + 4];
    int tid = threadIdx.x;
    int bm = blockIdx.x * GBM, bn = blockIdx.y * GBN;
    int lane = tid & 31, wid = tid >> 5;
    int wm = wid >> 1, wn = wid & 1;
    int g = lane >> 2, l4 = lane & 3;

    float acc[2][8][4];
#pragma unroll
    for (int mt = 0; mt < 2; mt++)
#pragma unroll
        for (int nt = 0; nt < 8; nt++)
#pragma unroll
            for (int c = 0; c < 4; c++) acc[mt][nt][c] = 0.f;

    float4 ra[4], rb[4];
    int T = K / GBK;

#pragma unroll
    for (int i = 0; i < 4; i++) {
        int idx = tid + i * 256;
        int row = idx >> 3, kq = idx & 7;
        int gr = bm + row;
        ra[i] = (gr < M) ? *(const float4*)&A[(size_t)gr * K + kq * 4]
                         : make_float4(0.f, 0.f, 0.f, 0.f);
        int r = idx >> 5, c4 = idx & 31;
        rb[i] = *(const float4*)&B[(size_t)r * 256 + bn + c4 * 4];
    }

    for (int t = 0; t < T; t++) {
#pragma unroll
        for (int i = 0; i < 4; i++) {
            int idx = tid + i * 256;
            int row = idx >> 3, kq = idx & 7;
            uint4 av = make_uint4(f2tf(ra[i].x), f2tf(ra[i].y), f2tf(ra[i].z), f2tf(ra[i].w));
            *(uint4*)&As[row][kq * 4] = av;
            int r = idx >> 5, c4 = idx & 31;
            uint4 bv = make_uint4(f2tf(rb[i].x), f2tf(rb[i].y), f2tf(rb[i].z), f2tf(rb[i].w));
            *(uint4*)&Bs[r][c4 * 4] = bv;
        }
        __syncthreads();

        if (t + 1 < T) {
            int k0 = (t + 1) * GBK;
#pragma unroll
            for (int i = 0; i < 4; i++) {
                int idx = tid + i * 256;
                int row = idx >> 3, kq = idx & 7;
                int gr = bm + row;
                ra[i] = (gr < M) ? *(const float4*)&A[(size_t)gr * K + k0 + kq * 4]
                                 : make_float4(0.f, 0.f, 0.f, 0.f);
                int r = idx >> 5, c4 = idx & 31;
                rb[i] = *(const float4*)&B[(size_t)(k0 + r) * 256 + bn + c4 * 4];
            }
        }

#pragma unroll
        for (int ks = 0; ks < 4; ks++) {
            int kb = ks * 8;
            unsigned a[2][4];
#pragma unroll
            for (int mt = 0; mt < 2; mt++) {
                int row = wm * 32 + mt * 16 + g;
                a[mt][0] = As[row][kb + l4];
                a[mt][1] = As[row + 8][kb + l4];
                a[mt][2] = As[row][kb + l4 + 4];
                a[mt][3] = As[row + 8][kb + l4 + 4];
            }
#pragma unroll
            for (int nt = 0; nt < 8; nt++) {
                int col = wn * 64 + nt * 8 + g;
                unsigned b0 = Bs[kb + l4][col];
                unsigned b1 = Bs[kb + l4 + 4][col];
                mma_tf32(acc[0][nt], a[0], b0, b1);
                mma_tf32(acc[1][nt], a[1], b0, b1);
            }
        }
        __syncthreads();
    }

#pragma unroll
    for (int mt = 0; mt < 2; mt++) {
#pragma unroll
        for (int nt = 0; nt < 8; nt++) {
            int row0 = bm + wm * 32 + mt * 16 + g;
            int col = bn + wn * 64 + nt * 8 + l4 * 2;
            if (row0 < M)
                *(float2*)&C[(size_t)row0 * 256 + col] = make_float2(acc[mt][nt][0], acc[mt][nt][1]);
            if (row0 + 8 < M)
                *(float2*)&C[(size_t)(row0 + 8) * 256 + col] = make_float2(acc[mt][nt][2], acc[mt][nt][3]);
        }
    }
}

// ---------------- per-node attention coefficients (H=4, C=64), float4 ----------------
__global__ void node_alpha4_kernel(const float* __restrict__ h,
                                   const float* __restrict__ a_s,
                                   const float* __restrict__ a_d,
                                   float* __restrict__ as, float* __restrict__ ad, int n) {
    int gt = blockIdx.x * blockDim.x + threadIdx.x;
    int warp = gt >> 5;
    int lane = gt & 31;
    if (warp >= n) return;
    const float4* hr = (const float4*)(h + (size_t)warp * 256);
    const float4* s4 = (const float4*)a_s;
    const float4* d4 = (const float4*)a_d;
    float4 v0 = hr[lane * 2], v1 = hr[lane * 2 + 1];
    float4 sa = s4[lane * 2], sb = s4[lane * 2 + 1];
    float4 da = d4[lane * 2], db = d4[lane * 2 + 1];
    float s = v0.x * sa.x + v0.y * sa.y + v0.z * sa.z + v0.w * sa.w +
              v1.x * sb.x + v1.y * sb.y + v1.z * sb.z + v1.w * sb.w;
    float d = v0.x * da.x + v0.y * da.y + v0.z * da.z + v0.w * da.w +
              v1.x * db.x + v1.y * db.y + v1.z * db.z + v1.w * db.w;
    // reduce within groups of 8 lanes (one head per group)
#pragma unroll
    for (int o = 1; o < 8; o <<= 1) {
        s += __shfl_xor_sync(0xffffffffu, s, o);
        d += __shfl_xor_sync(0xffffffffu, d, o);
    }
    if ((lane & 7) == 0) {
        int hh = lane >> 3;
        as[warp * 4 + hh] = s;
        ad[warp * 4 + hh] = d;
    }
}

__device__ __forceinline__ float lrelu(float v) { return v > 0.f ? v : 0.2f * v; }

// ---------------- warp-per-(node,head) single-pass aggregation ----------------
__global__ __launch_bounds__(256) void agg_warp_kernel(const float* __restrict__ h,
                                                       const int* __restrict__ csr_src,
                                                       const int* __restrict__ offs,
                                                       const int* __restrict__ deg,
                                                       const float* __restrict__ as,
                                                       const float* __restrict__ ad,
                                                       const float* __restrict__ bias,
                                                       float* __restrict__ out,
                                                       int n, int do_relu) {
    int gw = (blockIdx.x * blockDim.x + threadIdx.x) >> 5;
    int lane = threadIdx.x & 31;
    if (gw >= n * 4) return;
    int node = gw >> 2, head = gw & 3;
    int st = offs[node], d = deg[node];
    float adn = ad[node * 4 + head];

    float m = -1e30f, z = 0.f;
    float ax = 0.f, ay = 0.f;
    const float* hb = h + head * 64 + lane * 2;

    for (int base = 0; base < d; base += 32) {
        int cnt = min(32, d - base);
        int src = (lane < cnt) ? csr_src[st + base + lane] : 0;
        float e = (lane < cnt) ? lrelu(as[src * 4 + head] + adn) : -1e30f;
        // chunk max
        float cm = e;
#pragma unroll
        for (int o = 16; o; o >>= 1) cm = fmaxf(cm, __shfl_xor_sync(0xffffffffu, cm, o));
        float nm = fmaxf(m, cm);
        float scale = __expf(m - nm);
        float p = __expf(e - nm);
        float ps = p;
#pragma unroll
        for (int o = 16; o; o >>= 1) ps += __shfl_xor_sync(0xffffffffu, ps, o);
        z = z * scale + ps;
        ax *= scale;
        ay *= scale;
        m = nm;
#pragma unroll 4
        for (int q = 0; q < cnt; q++) {
            int s = __shfl_sync(0xffffffffu, src, q);
            float pq = __shfl_sync(0xffffffffu, p, q);
            float2 hv = *(const float2*)&hb[(size_t)s * 256];
            ax += pq * hv.x;
            ay += pq * hv.y;
        }
    }
    float rz = 1.f / (z + 1e-16f);
    int col = head * 64 + lane * 2;
    float ox = ax * rz + bias[col];
    float oy = ay * rz + bias[col + 1];
    if (do_relu) {
        ox = fmaxf(ox, 0.f);
        oy = fmaxf(oy, 0.f);
    }
    *(float2*)&out[(size_t)node * 256 + col] = make_float2(ox, oy);
}

// ---------------- layer3: GEMM [N,256]@[256,2] fused with alpha coeffs ----------------
__global__ void gemm3_alpha_kernel(const float* __restrict__ h, const float* __restrict__ W3,
                                   const float* __restrict__ a_s, const float* __restrict__ a_d,
                                   float* __restrict__ h3, float* __restrict__ as,
                                   float* __restrict__ ad, int n) {
    __shared__ float w[512];
    for (int i = threadIdx.x; i < 512; i += blockDim.x) w[i] = W3[i];
    __syncthreads();
    int gt = blockIdx.x * blockDim.x + threadIdx.x;
    int warp = gt >> 5;
    int lane = gt & 31;
    if (warp >= n) return;
    const float* hr = h + (size_t)warp * 256;
    float a0 = 0.f, a1 = 0.f;
#pragma unroll
    for (int k = 0; k < 8; k++) {
        int i = lane + 32 * k;
        float v = hr[i];
        a0 += v * w[i * 2];
        a1 += v * w[i * 2 + 1];
    }
#pragma unroll
    for (int o = 16; o; o >>= 1) {
        a0 += __shfl_xor_sync(0xffffffffu, a0, o);
        a1 += __shfl_xor_sync(0xffffffffu, a1, o);
    }
    if (lane == 0) {
        h3[2 * warp] = a0;
        h3[2 * warp + 1] = a1;
        as[warp] = a0 * a_s[0] + a1 * a_s[1];
        ad[warp] = a0 * a_d[0] + a1 * a_d[1];
    }
}

// ---------------- layer3 fused aggregation (H=1, C=2) ----------------
__global__ void agg3_fused_kernel(const float* __restrict__ h3, const int* __restrict__ csr_src,
                                  const int* __restrict__ offs, const int* __restrict__ deg,
                                  const float* __restrict__ as, const float* __restrict__ ad,
                                  const float* __restrict__ bias, float* __restrict__ out, int n) {
    int i = blockIdx.x * blockDim.x + threadIdx.x;
    if (i >= n) return;
    int st = offs[i], d = deg[i];
    float adn = ad[i];
    float mt = -1e30f, zt = 0.f;
    float a0 = 0.f, a1 = 0.f;
    for (int k = 0; k < d; k++) {
        int s = csr_src[st + k];
        float e = lrelu(as[s] + adn);
        float nm = fmaxf(mt, e);
        float scale = __expf(mt - nm);
        float p = __expf(e - nm);
        zt = zt * scale + p;
        a0 = a0 * scale + p * h3[2 * s];
        a1 = a1 * scale + p * h3[2 * s + 1];
        mt = nm;
    }
    float rz = 1.f / (zt + 1e-16f);
    out[2 * i] = a0 * rz + bias[0];
    out[2 * i + 1] = a1 * rz + bias[1];
}

// ---------------- launcher ----------------
extern "C" void kernel_launch(void* const* d_in, const int* in_sizes, int n_in,
                              void* d_out, int out_size) {
    const float* x   = (const float*)d_in[0];
    const int*   ei  = (const int*)d_in[1];
    const float* W1  = (const float*)d_in[2];
    const float* as1 = (const float*)d_in[3];
    const float* ad1 = (const float*)d_in[4];
    const float* b1  = (const float*)d_in[5];
    const float* W2  = (const float*)d_in[6];
    const float* as2 = (const float*)d_in[7];
    const float* ad2 = (const float*)d_in[8];
    const float* b2  = (const float*)d_in[9];
    const float* W3  = (const float*)d_in[10];
    const float* as3 = (const float*)d_in[11];
    const float* ad3 = (const float*)d_in[12];
    const float* b3  = (const float*)d_in[13];
    float* outp = (float*)d_out;

    int n = in_sizes[0] / 128;
    int E = in_sizes[1] / 2;

    float *hbuf, *aggbuf, *h3, *as, *ad;
    int *deg, *offs, *cursor, *bsum, *csr_src;
    cudaGetSymbolAddress((void**)&hbuf, g_hbuf);
    cudaGetSymbolAddress((void**)&aggbuf, g_aggbuf);
    cudaGetSymbolAddress((void**)&h3, g_h3);
    cudaGetSymbolAddress((void**)&as, g_as);
    cudaGetSymbolAddress((void**)&ad, g_ad);
    cudaGetSymbolAddress((void**)&deg, g_deg);
    cudaGetSymbolAddress((void**)&offs, g_offs);
    cudaGetSymbolAddress((void**)&cursor, g_cursor);
    cudaGetSymbolAddress((void**)&bsum, g_bsum);
    cudaGetSymbolAddress((void**)&csr_src, g_csr_src);

    int nb = cdiv(n, 256);

    // ---- CSR build ----
    fill_i32<<<cdiv(n, 256), 256>>>(deg, 0, n);
    hist_kernel<<<cdiv(E, 256), 256>>>(ei, deg, E);
    scan_block_kernel<<<nb, 256>>>(deg, offs, bsum, n);
    scan_sums_kernel<<<1, 256>>>(bsum, nb);
    scan_add_kernel<<<nb, 256>>>(offs, cursor, bsum, n);
    scatter_kernel<<<cdiv(E, 256), 256>>>(ei, cursor, csr_src, E);

    dim3 gemm_grid(cdiv(n, 128), 2);
    int agg_blocks = cdiv(n * 4 * 32, 256);

    // ---- Layer 1 ----
    mma_gemm_kernel<<<gemm_grid, 256>>>(x, W1, hbuf, n, 128);
    node_alpha4_kernel<<<cdiv(n * 32, 256), 256>>>(hbuf, as1, ad1, as, ad, n);
    agg_warp_kernel<<<agg_blocks, 256>>>(hbuf, csr_src, offs, deg, as, ad, b1, aggbuf, n, 1);

    // ---- Layer 2 ----
    mma_gemm_kernel<<<gemm_grid, 256>>>(aggbuf, W2, hbuf, n, 256);
    node_alpha4_kernel<<<cdiv(n * 32, 256), 256>>>(hbuf, as2, ad2, as, ad, n);
    agg_warp_kernel<<<agg_blocks, 256>>>(hbuf, csr_src, offs, deg, as, ad, b2, aggbuf, n, 1);

    // ---- Layer 3 ----
    gemm3_alpha_kernel<<<cdiv(n * 32, 256), 256>>>(aggbuf, W3, as3, ad3, h3, as, ad, n);
    agg3_fused_kernel<<<cdiv(n, 256), 256>>>(h3, csr_src, offs, deg, as, ad, b3, outp, n);
}

// round 5
// speedup vs baseline: 2.0696x; 1.0348x over previous
#include <cuda_runtime.h>
#include <math.h>
#include <limits.h>

#define NMAX 50000
#define EMAX 800000
#define HCMAX 256

// ---------------- scratch ----------------
__device__ float g_hbuf[NMAX * HCMAX];
__device__ float g_aggbuf[NMAX * HCMAX];
__device__ float g_h3[NMAX * 2];
__device__ float g_as[NMAX * 4];
__device__ float g_ad[NMAX * 4];
__device__ int   g_deg[NMAX];
__device__ int   g_offs[NMAX];
__device__ int   g_cursor[NMAX];
__device__ int   g_bsum[256];
__device__ int   g_csr_src[EMAX];

static inline int cdiv(int a, int b) { return (a + b - 1) / b; }

// ---------------- utility ----------------
__global__ void fill_i32(int* p, int v, int n) {
    int i = blockIdx.x * blockDim.x + threadIdx.x;
    if (i < n) p[i] = v;
}

// ---------------- CSR build ----------------
__global__ void hist_kernel(const int* __restrict__ ei, int* __restrict__ deg, int E) {
    int i = blockIdx.x * blockDim.x + threadIdx.x;
    if (i < E) atomicAdd(&deg[ei[E + i]], 1);
}

__global__ void scan_block_kernel(const int* __restrict__ deg, int* __restrict__ offs,
                                  int* __restrict__ bsum, int n) {
    __shared__ int ws[8];
    int t = threadIdx.x, lane = t & 31, w = t >> 5;
    int i = blockIdx.x * 256 + t;
    int v = (i < n) ? deg[i] : 0;
    int x = v;
#pragma unroll
    for (int o = 1; o < 32; o <<= 1) {
        int tv = __shfl_up_sync(0xffffffffu, x, o);
        if (lane >= o) x += tv;
    }
    if (lane == 31) ws[w] = x;
    __syncthreads();
    if (w == 0) {
        int y = (lane < 8) ? ws[lane] : 0;
#pragma unroll
        for (int o = 1; o < 8; o <<= 1) {
            int tv = __shfl_up_sync(0xffffffffu, y, o);
            if (lane >= o) y += tv;
        }
        if (lane < 8) ws[lane] = y;
    }
    __syncthreads();
    int woff = w ? ws[w - 1] : 0;
    if (i < n) offs[i] = woff + x - v;
    if (t == 255) bsum[blockIdx.x] = ws[7];
}

__global__ void scan_sums_kernel(int* bsum, int nb) {
    __shared__ int ws[8];
    int t = threadIdx.x, lane = t & 31, w = t >> 5;
    int v = (t < nb) ? bsum[t] : 0;
    int x = v;
#pragma unroll
    for (int o = 1; o < 32; o <<= 1) {
        int tv = __shfl_up_sync(0xffffffffu, x, o);
        if (lane >= o) x += tv;
    }
    if (lane == 31) ws[w] = x;
    __syncthreads();
    if (w == 0) {
        int y = (lane < 8) ? ws[lane] : 0;
#pragma unroll
        for (int o = 1; o < 8; o <<= 1) {
            int tv = __shfl_up_sync(0xffffffffu, y, o);
            if (lane >= o) y += tv;
        }
        if (lane < 8) ws[lane] = y;
    }
    __syncthreads();
    int woff = w ? ws[w - 1] : 0;
    if (t < nb) bsum[t] = woff + x - v;
}

__global__ void scan_add_kernel(int* __restrict__ offs, int* __restrict__ cursor,
                                const int* __restrict__ bsum, int n) {
    int i = blockIdx.x * blockDim.x + threadIdx.x;
    if (i < n) {
        int o = offs[i] + bsum[blockIdx.x];
        offs[i] = o;
        cursor[i] = o;
    }
}

__global__ void scatter_kernel(const int* __restrict__ ei, int* __restrict__ cursor,
                               int* __restrict__ csr_src, int E) {
    int i = blockIdx.x * blockDim.x + threadIdx.x;
    if (i >= E) return;
    int s = ei[i];
    int d = ei[E + i];
    int p = atomicAdd(&cursor[d], 1);
    csr_src[p] = s;
}

// ---------------- tf32 tensor-core GEMM + fused alpha epilogue ----------------
// C[M,256] = A[M,K] @ B[K,256]; as_out[r,head] = C[r,:head]·a_src, same for ad_out.
__device__ __forceinline__ unsigned f2tf(float x) {
    unsigned u;
    asm("cvt.rna.tf32.f32 %0, %1;" : "=r"(u) : "f"(x));
    return u;
}

__device__ __forceinline__ void mma_tf32(float* c, const unsigned* a, unsigned b0, unsigned b1) {
    asm volatile(
        "mma.sync.aligned.m16n8k8.row.col.f32.tf32.tf32.f32 "
        "{%0,%1,%2,%3},{%4,%5,%6,%7},{%8,%9},{%0,%1,%2,%3};"
        : "+f"(c[0]), "+f"(c[1]), "+f"(c[2]), "+f"(c[3])
        : "r"(a[0]), "r"(a[1]), "r"(a[2]), "r"(a[3]), "r"(b0), "r"(b1));
}

#define GBM 128
#define GBN 128
#define GBK 32

__global__ __launch_bounds__(256) void mma_gemm_kernel(const float* __restrict__ A,
                                                       const float* __restrict__ B,
                                                       float* __restrict__ C,
                                                       const float* __restrict__ a_src,
                                                       const float* __restrict__ a_dst,
                                                       float* __restrict__ as_out,
                                                       float* __restrict__ ad_out,
                                                       int M, int K) {
    __shared__ unsigned As[GBM][GBK + 4];
    __shared__ unsigned Bs[GBK][GBN + 4];
    int tid = threadIdx.x;
    int bm = blockIdx.x * GBM, bn = blockIdx.y * GBN;
    int lane = tid & 31, wid = tid >> 5;
    int wm = wid >> 1, wn = wid & 1;
    int g = lane >> 2, l4 = lane & 3;

    float acc[2][8][4];
#pragma unroll
    for (int mt = 0; mt < 2; mt++)
#pragma unroll
        for (int nt = 0; nt < 8; nt++)
#pragma unroll
            for (int c = 0; c < 4; c++) acc[mt][nt][c] = 0.f;

    float4 ra[4], rb[4];
    int T = K / GBK;

#pragma unroll
    for (int i = 0; i < 4; i++) {
        int idx = tid + i * 256;
        int row = idx >> 3, kq = idx & 7;
        int gr = bm + row;
        ra[i] = (gr < M) ? *(const float4*)&A[(size_t)gr * K + kq * 4]
                         : make_float4(0.f, 0.f, 0.f, 0.f);
        int r = idx >> 5, c4 = idx & 31;
        rb[i] = *(const float4*)&B[(size_t)r * 256 + bn + c4 * 4];
    }

    for (int t = 0; t < T; t++) {
#pragma unroll
        for (int i = 0; i < 4; i++) {
            int idx = tid + i * 256;
            int row = idx >> 3, kq = idx & 7;
            uint4 av = make_uint4(f2tf(ra[i].x), f2tf(ra[i].y), f2tf(ra[i].z), f2tf(ra[i].w));
            *(uint4*)&As[row][kq * 4] = av;
            int r = idx >> 5, c4 = idx & 31;
            uint4 bv = make_uint4(f2tf(rb[i].x), f2tf(rb[i].y), f2tf(rb[i].z), f2tf(rb[i].w));
            *(uint4*)&Bs[r][c4 * 4] = bv;
        }
        __syncthreads();

        if (t + 1 < T) {
            int k0 = (t + 1) * GBK;
#pragma unroll
            for (int i = 0; i < 4; i++) {
                int idx = tid + i * 256;
                int row = idx >> 3, kq = idx & 7;
                int gr = bm + row;
                ra[i] = (gr < M) ? *(const float4*)&A[(size_t)gr * K + k0 + kq * 4]
                                 : make_float4(0.f, 0.f, 0.f, 0.f);
                int r = idx >> 5, c4 = idx & 31;
                rb[i] = *(const float4*)&B[(size_t)(k0 + r) * 256 + bn + c4 * 4];
            }
        }

#pragma unroll
        for (int ks = 0; ks < 4; ks++) {
            int kb = ks * 8;
            unsigned a[2][4];
#pragma unroll
            for (int mt = 0; mt < 2; mt++) {
                int row = wm * 32 + mt * 16 + g;
                a[mt][0] = As[row][kb + l4];
                a[mt][1] = As[row + 8][kb + l4];
                a[mt][2] = As[row][kb + l4 + 4];
                a[mt][3] = As[row + 8][kb + l4 + 4];
            }
#pragma unroll
            for (int nt = 0; nt < 8; nt++) {
                int col = wn * 64 + nt * 8 + g;
                unsigned b0 = Bs[kb + l4][col];
                unsigned b1 = Bs[kb + l4 + 4][col];
                mma_tf32(acc[0][nt], a[0], b0, b1);
                mma_tf32(acc[1][nt], a[1], b0, b1);
            }
        }
        __syncthreads();
    }

    // C store
#pragma unroll
    for (int mt = 0; mt < 2; mt++) {
#pragma unroll
        for (int nt = 0; nt < 8; nt++) {
            int row0 = bm + wm * 32 + mt * 16 + g;
            int col = bn + wn * 64 + nt * 8 + l4 * 2;
            if (row0 < M)
                *(float2*)&C[(size_t)row0 * 256 + col] = make_float2(acc[mt][nt][0], acc[mt][nt][1]);
            if (row0 + 8 < M)
                *(float2*)&C[(size_t)(row0 + 8) * 256 + col] = make_float2(acc[mt][nt][2], acc[mt][nt][3]);
        }
    }

    // fused alpha epilogue: this warp covers one head's 64 channels for 32 rows
    int head = (bn + wn * 64) >> 6;
    const float* asv = a_src + head * 64;
    const float* adv = a_dst + head * 64;
#pragma unroll
    for (int mt = 0; mt < 2; mt++) {
        float sA = 0.f, dA = 0.f, sB = 0.f, dB = 0.f;
#pragma unroll
        for (int nt = 0; nt < 8; nt++) {
            int lc = nt * 8 + l4 * 2;
            float w0 = __ldg(&asv[lc]), w1 = __ldg(&asv[lc + 1]);
            float u0 = __ldg(&adv[lc]), u1 = __ldg(&adv[lc + 1]);
            sA += acc[mt][nt][0] * w0 + acc[mt][nt][1] * w1;
            dA += acc[mt][nt][0] * u0 + acc[mt][nt][1] * u1;
            sB += acc[mt][nt][2] * w0 + acc[mt][nt][3] * w1;
            dB += acc[mt][nt][2] * u0 + acc[mt][nt][3] * u1;
        }
#pragma unroll
        for (int o = 1; o < 4; o <<= 1) {
            sA += __shfl_xor_sync(0xffffffffu, sA, o);
            dA += __shfl_xor_sync(0xffffffffu, dA, o);
            sB += __shfl_xor_sync(0xffffffffu, sB, o);
            dB += __shfl_xor_sync(0xffffffffu, dB, o);
        }
        if (l4 == 0) {
            int row0 = bm + wm * 32 + mt * 16 + g;
            if (row0 < M) {
                as_out[row0 * 4 + head] = sA;
                ad_out[row0 * 4 + head] = dA;
            }
            if (row0 + 8 < M) {
                as_out[(row0 + 8) * 4 + head] = sB;
                ad_out[(row0 + 8) * 4 + head] = dB;
            }
        }
    }
}

__device__ __forceinline__ float lrelu(float v) { return v > 0.f ? v : 0.2f * v; }

// ---------------- warp-per-(node,head) single-pass aggregation ----------------
__global__ __launch_bounds__(256) void agg_warp_kernel(const float* __restrict__ h,
                                                       const int* __restrict__ csr_src,
                                                       const int* __restrict__ offs,
                                                       const int* __restrict__ deg,
                                                       const float* __restrict__ as,
                                                       const float* __restrict__ ad,
                                                       const float* __restrict__ bias,
                                                       float* __restrict__ out,
                                                       int n, int do_relu) {
    int gw = (blockIdx.x * blockDim.x + threadIdx.x) >> 5;
    int lane = threadIdx.x & 31;
    if (gw >= n * 4) return;
    int node = gw >> 2, head = gw & 3;
    int st = offs[node], d = deg[node];
    float adn = ad[node * 4 + head];

    float m = -1e30f, z = 0.f;
    float ax = 0.f, ay = 0.f;
    const float* hb = h + head * 64 + lane * 2;

    for (int base = 0; base < d; base += 32) {
        int cnt = min(32, d - base);
        int src = (lane < cnt) ? csr_src[st + base + lane] : 0;
        float e = (lane < cnt) ? lrelu(as[src * 4 + head] + adn) : -1e30f;
        float cm = e;
#pragma unroll
        for (int o = 16; o; o >>= 1) cm = fmaxf(cm, __shfl_xor_sync(0xffffffffu, cm, o));
        float nm = fmaxf(m, cm);
        float scale = __expf(m - nm);
        float p = __expf(e - nm);
        float ps = p;
#pragma unroll
        for (int o = 16; o; o >>= 1) ps += __shfl_xor_sync(0xffffffffu, ps, o);
        z = z * scale + ps;
        ax *= scale;
        ay *= scale;
        m = nm;
#pragma unroll 4
        for (int q = 0; q < cnt; q++) {
            int s = __shfl_sync(0xffffffffu, src, q);
            float pq = __shfl_sync(0xffffffffu, p, q);
            float2 hv = *(const float2*)&hb[(size_t)s * 256];
            ax += pq * hv.x;
            ay += pq * hv.y;
        }
    }
    float rz = 1.f / (z + 1e-16f);
    int col = head * 64 + lane * 2;
    float ox = ax * rz + bias[col];
    float oy = ay * rz + bias[col + 1];
    if (do_relu) {
        ox = fmaxf(ox, 0.f);
        oy = fmaxf(oy, 0.f);
    }
    *(float2*)&out[(size_t)node * 256 + col] = make_float2(ox, oy);
}

// ---------------- layer3: GEMM [N,256]@[256,2] fused with alpha coeffs ----------------
__global__ void gemm3_alpha_kernel(const float* __restrict__ h, const float* __restrict__ W3,
                                   const float* __restrict__ a_s, const float* __restrict__ a_d,
                                   float* __restrict__ h3, float* __restrict__ as,
                                   float* __restrict__ ad, int n) {
    __shared__ float w[512];
    for (int i = threadIdx.x; i < 512; i += blockDim.x) w[i] = W3[i];
    __syncthreads();
    int gt = blockIdx.x * blockDim.x + threadIdx.x;
    int warp = gt >> 5;
    int lane = gt & 31;
    if (warp >= n) return;
    const float* hr = h + (size_t)warp * 256;
    float a0 = 0.f, a1 = 0.f;
#pragma unroll
    for (int k = 0; k < 8; k++) {
        int i = lane + 32 * k;
        float v = hr[i];
        a0 += v * w[i * 2];
        a1 += v * w[i * 2 + 1];
    }
#pragma unroll
    for (int o = 16; o; o >>= 1) {
        a0 += __shfl_xor_sync(0xffffffffu, a0, o);
        a1 += __shfl_xor_sync(0xffffffffu, a1, o);
    }
    if (lane == 0) {
        h3[2 * warp] = a0;
        h3[2 * warp + 1] = a1;
        as[warp] = a0 * a_s[0] + a1 * a_s[1];
        ad[warp] = a0 * a_d[0] + a1 * a_d[1];
    }
}

// ---------------- layer3 fused aggregation (H=1, C=2) ----------------
__global__ void agg3_fused_kernel(const float* __restrict__ h3, const int* __restrict__ csr_src,
                                  const int* __restrict__ offs, const int* __restrict__ deg,
                                  const float* __restrict__ as, const float* __restrict__ ad,
                                  const float* __restrict__ bias, float* __restrict__ out, int n) {
    int i = blockIdx.x * blockDim.x + threadIdx.x;
    if (i >= n) return;
    int st = offs[i], d = deg[i];
    float adn = ad[i];
    float mt = -1e30f, zt = 0.f;
    float a0 = 0.f, a1 = 0.f;
    for (int k = 0; k < d; k++) {
        int s = csr_src[st + k];
        float e = lrelu(as[s] + adn);
        float nm = fmaxf(mt, e);
        float scale = __expf(mt - nm);
        float p = __expf(e - nm);
        zt = zt * scale + p;
        a0 = a0 * scale + p * h3[2 * s];
        a1 = a1 * scale + p * h3[2 * s + 1];
        mt = nm;
    }
    float rz = 1.f / (zt + 1e-16f);
    out[2 * i] = a0 * rz + bias[0];
    out[2 * i + 1] = a1 * rz + bias[1];
}

// ---------------- launcher ----------------
extern "C" void kernel_launch(void* const* d_in, const int* in_sizes, int n_in,
                              void* d_out, int out_size) {
    const float* x   = (const float*)d_in[0];
    const int*   ei  = (const int*)d_in[1];
    const float* W1  = (const float*)d_in[2];
    const float* as1 = (const float*)d_in[3];
    const float* ad1 = (const float*)d_in[4];
    const float* b1  = (const float*)d_in[5];
    const float* W2  = (const float*)d_in[6];
    const float* as2 = (const float*)d_in[7];
    const float* ad2 = (const float*)d_in[8];
    const float* b2  = (const float*)d_in[9];
    const float* W3  = (const float*)d_in[10];
    const float* as3 = (const float*)d_in[11];
    const float* ad3 = (const float*)d_in[12];
    const float* b3  = (const float*)d_in[13];
    float* outp = (float*)d_out;

    int n = in_sizes[0] / 128;
    int E = in_sizes[1] / 2;

    float *hbuf, *aggbuf, *h3, *as, *ad;
    int *deg, *offs, *cursor, *bsum, *csr_src;
    cudaGetSymbolAddress((void**)&hbuf, g_hbuf);
    cudaGetSymbolAddress((void**)&aggbuf, g_aggbuf);
    cudaGetSymbolAddress((void**)&h3, g_h3);
    cudaGetSymbolAddress((void**)&as, g_as);
    cudaGetSymbolAddress((void**)&ad, g_ad);
    cudaGetSymbolAddress((void**)&deg, g_deg);
    cudaGetSymbolAddress((void**)&offs, g_offs);
    cudaGetSymbolAddress((void**)&cursor, g_cursor);
    cudaGetSymbolAddress((void**)&bsum, g_bsum);
    cudaGetSymbolAddress((void**)&csr_src, g_csr_src);

    int nb = cdiv(n, 256);
    dim3 gemm_grid(cdiv(n, 128), 2);
    int agg_blocks = cdiv(n * 4 * 32, 256);

    // CSR build interleaved with GEMM1 (independent); GEMM1 sits at launch
    // index 3 so the profiler samples it.
    fill_i32<<<cdiv(n, 256), 256>>>(deg, 0, n);                       // 0
    hist_kernel<<<cdiv(E, 256), 256>>>(ei, deg, E);                   // 1
    scan_block_kernel<<<nb, 256>>>(deg, offs, bsum, n);               // 2
    mma_gemm_kernel<<<gemm_grid, 256>>>(x, W1, hbuf, as1, ad1, as, ad, n, 128);  // 3 (profiled)
    scan_sums_kernel<<<1, 256>>>(bsum, nb);                           // 4
    scan_add_kernel<<<nb, 256>>>(offs, cursor, bsum, n);              // 5
    scatter_kernel<<<cdiv(E, 256), 256>>>(ei, cursor, csr_src, E);    // 6

    // ---- Layer 1 aggregation ----
    agg_warp_kernel<<<agg_blocks, 256>>>(hbuf, csr_src, offs, deg, as, ad, b1, aggbuf, n, 1);

    // ---- Layer 2 ----
    mma_gemm_kernel<<<gemm_grid, 256>>>(aggbuf, W2, hbuf, as2, ad2, as, ad, n, 256);
    agg_warp_kernel<<<agg_blocks, 256>>>(hbuf, csr_src, offs, deg, as, ad, b2, aggbuf, n, 1);

    // ---- Layer 3 ----
    gemm3_alpha_kernel<<<cdiv(n * 32, 256), 256>>>(aggbuf, W3, as3, ad3, h3, as, ad, n);
    agg3_fused_kernel<<<cdiv(n, 256), 256>>>(h3, csr_src, offs, deg, as, ad, b3, outp, n);
}

// round 6
// speedup vs baseline: 2.4706x; 1.1938x over previous
#include <cuda_runtime.h>
#include <math.h>
#include <limits.h>

#define NMAX 50000
#define EMAX 800000
#define HCMAX 256

// ---------------- scratch ----------------
__device__ float g_hbuf[NMAX * HCMAX];
__device__ float g_aggbuf[NMAX * HCMAX];
__device__ float g_xr[NMAX * 128];     // tf32-rounded x
__device__ float g_w1r[128 * 256];     // tf32-rounded W1
__device__ float g_w2r[256 * 256];     // tf32-rounded W2
__device__ float g_h3[NMAX * 2];
__device__ float g_as[NMAX * 4];
__device__ float g_ad[NMAX * 4];
__device__ int   g_deg[NMAX];
__device__ int   g_offs[NMAX];
__device__ int   g_cursor[NMAX];
__device__ int   g_bsum[256];
__device__ int   g_csr_src[EMAX];

static inline int cdiv(int a, int b) { return (a + b - 1) / b; }

__device__ __forceinline__ unsigned f2tf(float x) {
    unsigned u;
    asm("cvt.rna.tf32.f32 %0, %1;" : "=r"(u) : "f"(x));
    return u;
}
__device__ __forceinline__ float roundtf(float x) { return __uint_as_float(f2tf(x)); }

// ---------------- tf32 pre-round (elementwise) ----------------
__global__ void round_tf32_kernel(const float* __restrict__ in, float* __restrict__ out, int n4) {
    int i = blockIdx.x * blockDim.x + threadIdx.x;
    if (i >= n4) return;
    float4 v = ((const float4*)in)[i];
    v.x = roundtf(v.x); v.y = roundtf(v.y); v.z = roundtf(v.z); v.w = roundtf(v.w);
    ((float4*)out)[i] = v;
}

// ---------------- utility ----------------
__global__ void fill_i32(int* p, int v, int n) {
    int i = blockIdx.x * blockDim.x + threadIdx.x;
    if (i < n) p[i] = v;
}

// ---------------- CSR build ----------------
__global__ void hist_kernel(const int* __restrict__ ei, int* __restrict__ deg, int E) {
    int i = blockIdx.x * blockDim.x + threadIdx.x;
    if (i < E) atomicAdd(&deg[ei[E + i]], 1);
}

__global__ void scan_block_kernel(const int* __restrict__ deg, int* __restrict__ offs,
                                  int* __restrict__ bsum, int n) {
    __shared__ int ws[8];
    int t = threadIdx.x, lane = t & 31, w = t >> 5;
    int i = blockIdx.x * 256 + t;
    int v = (i < n) ? deg[i] : 0;
    int x = v;
#pragma unroll
    for (int o = 1; o < 32; o <<= 1) {
        int tv = __shfl_up_sync(0xffffffffu, x, o);
        if (lane >= o) x += tv;
    }
    if (lane == 31) ws[w] = x;
    __syncthreads();
    if (w == 0) {
        int y = (lane < 8) ? ws[lane] : 0;
#pragma unroll
        for (int o = 1; o < 8; o <<= 1) {
            int tv = __shfl_up_sync(0xffffffffu, y, o);
            if (lane >= o) y += tv;
        }
        if (lane < 8) ws[lane] = y;
    }
    __syncthreads();
    int woff = w ? ws[w - 1] : 0;
    if (i < n) offs[i] = woff + x - v;
    if (t == 255) bsum[blockIdx.x] = ws[7];
}

__global__ void scan_sums_kernel(int* bsum, int nb) {
    __shared__ int ws[8];
    int t = threadIdx.x, lane = t & 31, w = t >> 5;
    int v = (t < nb) ? bsum[t] : 0;
    int x = v;
#pragma unroll
    for (int o = 1; o < 32; o <<= 1) {
        int tv = __shfl_up_sync(0xffffffffu, x, o);
        if (lane >= o) x += tv;
    }
    if (lane == 31) ws[w] = x;
    __syncthreads();
    if (w == 0) {
        int y = (lane < 8) ? ws[lane] : 0;
#pragma unroll
        for (int o = 1; o < 8; o <<= 1) {
            int tv = __shfl_up_sync(0xffffffffu, y, o);
            if (lane >= o) y += tv;
        }
        if (lane < 8) ws[lane] = y;
    }
    __syncthreads();
    int woff = w ? ws[w - 1] : 0;
    if (t < nb) bsum[t] = woff + x - v;
}

__global__ void scan_add_kernel(int* __restrict__ offs, int* __restrict__ cursor,
                                const int* __restrict__ bsum, int n) {
    int i = blockIdx.x * blockDim.x + threadIdx.x;
    if (i < n) {
        int o = offs[i] + bsum[blockIdx.x];
        offs[i] = o;
        cursor[i] = o;
    }
}

__global__ void scatter_kernel(const int* __restrict__ ei, int* __restrict__ cursor,
                               int* __restrict__ csr_src, int E) {
    int i = blockIdx.x * blockDim.x + threadIdx.x;
    if (i >= E) return;
    int s = ei[i];
    int d = ei[E + i];
    int p = atomicAdd(&cursor[d], 1);
    csr_src[p] = s;
}

// ---------------- tf32 MMA GEMM, cp.async double-buffered ----------------
// Inputs must be pre-rounded to tf32-representable fp32.
__device__ __forceinline__ void mma_tf32(float* c, const unsigned* a, unsigned b0, unsigned b1) {
    asm volatile(
        "mma.sync.aligned.m16n8k8.row.col.f32.tf32.tf32.f32 "
        "{%0,%1,%2,%3},{%4,%5,%6,%7},{%8,%9},{%0,%1,%2,%3};"
        : "+f"(c[0]), "+f"(c[1]), "+f"(c[2]), "+f"(c[3])
        : "r"(a[0]), "r"(a[1]), "r"(a[2]), "r"(a[3]), "r"(b0), "r"(b1));
}

__device__ __forceinline__ void cpasync16(void* dst_smem, const void* src, bool pred) {
    unsigned d = (unsigned)__cvta_generic_to_shared(dst_smem);
    int sz = pred ? 16 : 0;
    asm volatile("cp.async.cg.shared.global [%0], [%1], 16, %2;\n" :: "r"(d), "l"(src), "r"(sz));
}

#define GBM 128
#define GBN 128
#define GBK 32
#define APITCH (GBK + 4)
#define BPITCH (GBN + 4)
#define ABUF (GBM * APITCH)
#define BBUF (GBK * BPITCH)
#define GEMM_SMEM ((2 * ABUF + 2 * BBUF) * 4)

__global__ __launch_bounds__(256, 2) void mma_gemm_kernel(const float* __restrict__ A,
                                                          const float* __restrict__ B,
                                                          float* __restrict__ C,
                                                          const float* __restrict__ a_src,
                                                          const float* __restrict__ a_dst,
                                                          float* __restrict__ as_out,
                                                          float* __restrict__ ad_out,
                                                          int M, int K) {
    extern __shared__ float smem[];
    float* sA = smem;               // 2 buffers of [GBM][APITCH]
    float* sB = smem + 2 * ABUF;    // 2 buffers of [GBK][BPITCH]
    int tid = threadIdx.x;
    int bm = blockIdx.x * GBM, bn = blockIdx.y * GBN;
    int lane = tid & 31, wid = tid >> 5;
    int wm = wid >> 1, wn = wid & 1;
    int g = lane >> 2, l4 = lane & 3;

    float acc[2][8][4];
#pragma unroll
    for (int mt = 0; mt < 2; mt++)
#pragma unroll
        for (int nt = 0; nt < 8; nt++)
#pragma unroll
            for (int c = 0; c < 4; c++) acc[mt][nt][c] = 0.f;

    int T = K / GBK;
    // A mapping: fid = tid + i*256 : row = fid>>3, kq = fid&7
    // B mapping: r = fid>>5, c4 = fid&31
    int arow = tid >> 3, akq = tid & 7;
    int br = tid >> 5, bc4 = tid & 31;

    // issue tile 0
    {
        float* a0 = sA;
        float* b0 = sB;
#pragma unroll
        for (int i = 0; i < 4; i++) {
            int row = arow + i * 32;
            int gr = bm + row;
            bool p = gr < M;
            int grc = p ? gr : 0;
            cpasync16(&a0[row * APITCH + akq * 4], &A[(size_t)grc * K + akq * 4], p);
            int r = br + i * 8;
            cpasync16(&b0[r * BPITCH + bc4 * 4], &B[(size_t)r * 256 + bn + bc4 * 4], true);
        }
        asm volatile("cp.async.commit_group;\n");
    }

    for (int t = 0; t < T; t++) {
        int cb = t & 1;
        if (t + 1 < T) {
            int k0 = (t + 1) * GBK;
            float* a1 = sA + ((t + 1) & 1) * ABUF;
            float* b1 = sB + ((t + 1) & 1) * BBUF;
#pragma unroll
            for (int i = 0; i < 4; i++) {
                int row = arow + i * 32;
                int gr = bm + row;
                bool p = gr < M;
                int grc = p ? gr : 0;
                cpasync16(&a1[row * APITCH + akq * 4], &A[(size_t)grc * K + k0 + akq * 4], p);
                int r = br + i * 8;
                cpasync16(&b1[r * BPITCH + bc4 * 4], &B[(size_t)(k0 + r) * 256 + bn + bc4 * 4], true);
            }
            asm volatile("cp.async.commit_group;\n");
            asm volatile("cp.async.wait_group 1;\n");
        } else {
            asm volatile("cp.async.wait_group 0;\n");
        }
        __syncthreads();

        const float* Ac = sA + cb * ABUF;
        const float* Bc = sB + cb * BBUF;
#pragma unroll
        for (int ks = 0; ks < 4; ks++) {
            int kb = ks * 8;
            unsigned a[2][4];
#pragma unroll
            for (int mt = 0; mt < 2; mt++) {
                int row = wm * 32 + mt * 16 + g;
                a[mt][0] = __float_as_uint(Ac[row * APITCH + kb + l4]);
                a[mt][1] = __float_as_uint(Ac[(row + 8) * APITCH + kb + l4]);
                a[mt][2] = __float_as_uint(Ac[row * APITCH + kb + l4 + 4]);
                a[mt][3] = __float_as_uint(Ac[(row + 8) * APITCH + kb + l4 + 4]);
            }
#pragma unroll
            for (int nt = 0; nt < 8; nt++) {
                int col = wn * 64 + nt * 8 + g;
                unsigned b0 = __float_as_uint(Bc[(kb + l4) * BPITCH + col]);
                unsigned b1 = __float_as_uint(Bc[(kb + l4 + 4) * BPITCH + col]);
                mma_tf32(acc[0][nt], a[0], b0, b1);
                mma_tf32(acc[1][nt], a[1], b0, b1);
            }
        }
        __syncthreads();
    }

    // C store
#pragma unroll
    for (int mt = 0; mt < 2; mt++) {
#pragma unroll
        for (int nt = 0; nt < 8; nt++) {
            int row0 = bm + wm * 32 + mt * 16 + g;
            int col = bn + wn * 64 + nt * 8 + l4 * 2;
            if (row0 < M)
                *(float2*)&C[(size_t)row0 * 256 + col] = make_float2(acc[mt][nt][0], acc[mt][nt][1]);
            if (row0 + 8 < M)
                *(float2*)&C[(size_t)(row0 + 8) * 256 + col] = make_float2(acc[mt][nt][2], acc[mt][nt][3]);
        }
    }

    // fused alpha epilogue: warp covers one head's 64 channels for 32 rows
    int head = (bn + wn * 64) >> 6;
    const float* asv = a_src + head * 64;
    const float* adv = a_dst + head * 64;
#pragma unroll
    for (int mt = 0; mt < 2; mt++) {
        float sA_ = 0.f, dA_ = 0.f, sB_ = 0.f, dB_ = 0.f;
#pragma unroll
        for (int nt = 0; nt < 8; nt++) {
            int lc = nt * 8 + l4 * 2;
            float w0 = __ldg(&asv[lc]), w1 = __ldg(&asv[lc + 1]);
            float u0 = __ldg(&adv[lc]), u1 = __ldg(&adv[lc + 1]);
            sA_ += acc[0][nt][0] * 0.f; // (placeholder removed below)
            sA_ += acc[mt][nt][0] * w0 + acc[mt][nt][1] * w1;
            dA_ += acc[mt][nt][0] * u0 + acc[mt][nt][1] * u1;
            sB_ += acc[mt][nt][2] * w0 + acc[mt][nt][3] * w1;
            dB_ += acc[mt][nt][2] * u0 + acc[mt][nt][3] * u1;
        }
#pragma unroll
        for (int o = 1; o < 4; o <<= 1) {
            sA_ += __shfl_xor_sync(0xffffffffu, sA_, o);
            dA_ += __shfl_xor_sync(0xffffffffu, dA_, o);
            sB_ += __shfl_xor_sync(0xffffffffu, sB_, o);
            dB_ += __shfl_xor_sync(0xffffffffu, dB_, o);
        }
        if (l4 == 0) {
            int row0 = bm + wm * 32 + mt * 16 + g;
            if (row0 < M) {
                as_out[row0 * 4 + head] = sA_;
                ad_out[row0 * 4 + head] = dA_;
            }
            if (row0 + 8 < M) {
                as_out[(row0 + 8) * 4 + head] = sB_;
                ad_out[(row0 + 8) * 4 + head] = dB_;
            }
        }
    }
}

__device__ __forceinline__ float lrelu(float v) { return v > 0.f ? v : 0.2f * v; }

// ---------------- warp-per-node aggregation: 8 channels/lane, 8-edge chunks ----------------
__global__ __launch_bounds__(256) void agg_warp_kernel(const float* __restrict__ h,
                                                       const int* __restrict__ csr_src,
                                                       const int* __restrict__ offs,
                                                       const int* __restrict__ deg,
                                                       const float* __restrict__ as,
                                                       const float* __restrict__ ad,
                                                       const float* __restrict__ bias,
                                                       float* __restrict__ out,
                                                       int n, int do_relu, int do_round) {
    int node = (blockIdx.x * blockDim.x + threadIdx.x) >> 5;
    int lane = threadIdx.x & 31;
    if (node >= n) return;
    int myhead = lane >> 3;      // head owning this lane's 8 channels
    int j = lane & 3;            // head role for e-computation
    int i = lane >> 2;           // edge slot 0..7 for e-computation
    int st = offs[node], d = deg[node];
    float adn = ad[node * 4 + j];

    float m = -1e30f, z = 0.f;   // softmax state for head j (replicated in group)
    float4 acc0 = make_float4(0.f, 0.f, 0.f, 0.f);
    float4 acc1 = make_float4(0.f, 0.f, 0.f, 0.f);

    for (int base = 0; base < d; base += 8) {
        int cnt = min(8, d - base);
        int src = (lane < cnt) ? csr_src[st + base + lane] : 0;
        int s_i = __shfl_sync(0xffffffffu, src, i);
        float e = (i < cnt) ? lrelu(as[s_i * 4 + j] + adn) : -1e30f;
        // per-head max over the 8 edge slots (groups: same lane&3)
        float cm = e;
#pragma unroll
        for (int o = 4; o < 32; o <<= 1) cm = fmaxf(cm, __shfl_xor_sync(0xffffffffu, cm, o));
        float nm = fmaxf(m, cm);
        float p = __expf(e - nm);
        float ps = p;
#pragma unroll
        for (int o = 4; o < 32; o <<= 1) ps += __shfl_xor_sync(0xffffffffu, ps, o);
        float scale = __expf(m - nm);
        z = z * scale + ps;
        m = nm;
        // rescale accumulator by my head's scale (lane 5*myhead has j==myhead)
        float scale_my = __shfl_sync(0xffffffffu, scale, myhead * 5);
        acc0.x *= scale_my; acc0.y *= scale_my; acc0.z *= scale_my; acc0.w *= scale_my;
        acc1.x *= scale_my; acc1.y *= scale_my; acc1.z *= scale_my; acc1.w *= scale_my;
#pragma unroll 8
        for (int q = 0; q < cnt; q++) {
            int s = __shfl_sync(0xffffffffu, src, q);
            float pq = __shfl_sync(0xffffffffu, p, q * 4 + myhead);
            const float4* hp = (const float4*)(h + (size_t)s * 256 + lane * 8);
            float4 v0 = hp[0], v1 = hp[1];
            acc0.x += pq * v0.x; acc0.y += pq * v0.y; acc0.z += pq * v0.z; acc0.w += pq * v0.w;
            acc1.x += pq * v1.x; acc1.y += pq * v1.y; acc1.z += pq * v1.z; acc1.w += pq * v1.w;
        }
    }
    float z_my = __shfl_sync(0xffffffffu, z, myhead * 5);
    float rz = 1.f / (z_my + 1e-16f);
    const float4* bp = (const float4*)(bias + lane * 8);
    float4 b0 = bp[0], b1 = bp[1];
    float4 o0, o1;
    o0.x = acc0.x * rz + b0.x; o0.y = acc0.y * rz + b0.y;
    o0.z = acc0.z * rz + b0.z; o0.w = acc0.w * rz + b0.w;
    o1.x = acc1.x * rz + b1.x; o1.y = acc1.y * rz + b1.y;
    o1.z = acc1.z * rz + b1.z; o1.w = acc1.w * rz + b1.w;
    if (do_relu) {
        o0.x = fmaxf(o0.x, 0.f); o0.y = fmaxf(o0.y, 0.f);
        o0.z = fmaxf(o0.z, 0.f); o0.w = fmaxf(o0.w, 0.f);
        o1.x = fmaxf(o1.x, 0.f); o1.y = fmaxf(o1.y, 0.f);
        o1.z = fmaxf(o1.z, 0.f); o1.w = fmaxf(o1.w, 0.f);
    }
    if (do_round) {
        o0.x = roundtf(o0.x); o0.y = roundtf(o0.y); o0.z = roundtf(o0.z); o0.w = roundtf(o0.w);
        o1.x = roundtf(o1.x); o1.y = roundtf(o1.y); o1.z = roundtf(o1.z); o1.w = roundtf(o1.w);
    }
    float4* op = (float4*)(out + (size_t)node * 256 + lane * 8);
    op[0] = o0;
    op[1] = o1;
}

// ---------------- layer3: GEMM [N,256]@[256,2] fused with alpha coeffs ----------------
__global__ void gemm3_alpha_kernel(const float* __restrict__ h, const float* __restrict__ W3,
                                   const float* __restrict__ a_s, const float* __restrict__ a_d,
                                   float* __restrict__ h3, float* __restrict__ as,
                                   float* __restrict__ ad, int n) {
    __shared__ float w[512];
    for (int i = threadIdx.x; i < 512; i += blockDim.x) w[i] = W3[i];
    __syncthreads();
    int gt = blockIdx.x * blockDim.x + threadIdx.x;
    int warp = gt >> 5;
    int lane = gt & 31;
    if (warp >= n) return;
    const float* hr = h + (size_t)warp * 256;
    float a0 = 0.f, a1 = 0.f;
#pragma unroll
    for (int k = 0; k < 8; k++) {
        int i = lane + 32 * k;
        float v = hr[i];
        a0 += v * w[i * 2];
        a1 += v * w[i * 2 + 1];
    }
#pragma unroll
    for (int o = 16; o; o >>= 1) {
        a0 += __shfl_xor_sync(0xffffffffu, a0, o);
        a1 += __shfl_xor_sync(0xffffffffu, a1, o);
    }
    if (lane == 0) {
        h3[2 * warp] = a0;
        h3[2 * warp + 1] = a1;
        as[warp] = a0 * a_s[0] + a1 * a_s[1];
        ad[warp] = a0 * a_d[0] + a1 * a_d[1];
    }
}

// ---------------- layer3 fused aggregation (H=1, C=2) ----------------
__global__ void agg3_fused_kernel(const float* __restrict__ h3, const int* __restrict__ csr_src,
                                  const int* __restrict__ offs, const int* __restrict__ deg,
                                  const float* __restrict__ as, const float* __restrict__ ad,
                                  const float* __restrict__ bias, float* __restrict__ out, int n) {
    int i = blockIdx.x * blockDim.x + threadIdx.x;
    if (i >= n) return;
    int st = offs[i], d = deg[i];
    float adn = ad[i];
    float mt = -1e30f, zt = 0.f;
    float a0 = 0.f, a1 = 0.f;
    for (int k = 0; k < d; k++) {
        int s = csr_src[st + k];
        float e = lrelu(as[s] + adn);
        float nm = fmaxf(mt, e);
        float scale = __expf(mt - nm);
        float p = __expf(e - nm);
        zt = zt * scale + p;
        a0 = a0 * scale + p * h3[2 * s];
        a1 = a1 * scale + p * h3[2 * s + 1];
        mt = nm;
    }
    float rz = 1.f / (zt + 1e-16f);
    out[2 * i] = a0 * rz + bias[0];
    out[2 * i + 1] = a1 * rz + bias[1];
}

// ---------------- launcher ----------------
extern "C" void kernel_launch(void* const* d_in, const int* in_sizes, int n_in,
                              void* d_out, int out_size) {
    const float* x   = (const float*)d_in[0];
    const int*   ei  = (const int*)d_in[1];
    const float* W1  = (const float*)d_in[2];
    const float* as1 = (const float*)d_in[3];
    const float* ad1 = (const float*)d_in[4];
    const float* b1  = (const float*)d_in[5];
    const float* W2  = (const float*)d_in[6];
    const float* as2 = (const float*)d_in[7];
    const float* ad2 = (const float*)d_in[8];
    const float* b2  = (const float*)d_in[9];
    const float* W3  = (const float*)d_in[10];
    const float* as3 = (const float*)d_in[11];
    const float* ad3 = (const float*)d_in[12];
    const float* b3  = (const float*)d_in[13];
    float* outp = (float*)d_out;

    int n = in_sizes[0] / 128;
    int E = in_sizes[1] / 2;

    float *hbuf, *aggbuf, *xr, *w1r, *w2r, *h3, *as, *ad;
    int *deg, *offs, *cursor, *bsum, *csr_src;
    cudaGetSymbolAddress((void**)&hbuf, g_hbuf);
    cudaGetSymbolAddress((void**)&aggbuf, g_aggbuf);
    cudaGetSymbolAddress((void**)&xr, g_xr);
    cudaGetSymbolAddress((void**)&w1r, g_w1r);
    cudaGetSymbolAddress((void**)&w2r, g_w2r);
    cudaGetSymbolAddress((void**)&h3, g_h3);
    cudaGetSymbolAddress((void**)&as, g_as);
    cudaGetSymbolAddress((void**)&ad, g_ad);
    cudaGetSymbolAddress((void**)&deg, g_deg);
    cudaGetSymbolAddress((void**)&offs, g_offs);
    cudaGetSymbolAddress((void**)&cursor, g_cursor);
    cudaGetSymbolAddress((void**)&bsum, g_bsum);
    cudaGetSymbolAddress((void**)&csr_src, g_csr_src);

    cudaFuncSetAttribute(mma_gemm_kernel, cudaFuncAttributeMaxDynamicSharedMemorySize, GEMM_SMEM);

    int nb = cdiv(n, 256);
    dim3 gemm_grid(cdiv(n, 128), 2);
    int agg_blocks = cdiv(n * 32, 256);

    // pre-round inputs to tf32-representable fp32
    round_tf32_kernel<<<cdiv(n * 128 / 4, 256), 256>>>(x, xr, n * 128 / 4);     // 0
    round_tf32_kernel<<<cdiv(128 * 256 / 4, 256), 256>>>(W1, w1r, 128 * 256 / 4); // 1
    round_tf32_kernel<<<cdiv(256 * 256 / 4, 256), 256>>>(W2, w2r, 256 * 256 / 4); // 2

    // GEMM1 at launch idx 3 (profiled)
    mma_gemm_kernel<<<gemm_grid, 256, GEMM_SMEM>>>(xr, w1r, hbuf, as1, ad1, as, ad, n, 128); // 3

    // CSR build
    fill_i32<<<cdiv(n, 256), 256>>>(deg, 0, n);                       // 4
    hist_kernel<<<cdiv(E, 256), 256>>>(ei, deg, E);                   // 5
    scan_block_kernel<<<nb, 256>>>(deg, offs, bsum, n);               // 6
    scan_sums_kernel<<<1, 256>>>(bsum, nb);                           // 7
    scan_add_kernel<<<nb, 256>>>(offs, cursor, bsum, n);              // 8
    scatter_kernel<<<cdiv(E, 256), 256>>>(ei, cursor, csr_src, E);    // 9

    // Layer 1 aggregation (round output for GEMM2's A operand)
    agg_warp_kernel<<<agg_blocks, 256>>>(hbuf, csr_src, offs, deg, as, ad, b1, aggbuf, n, 1, 1);

    // Layer 2
    mma_gemm_kernel<<<gemm_grid, 256, GEMM_SMEM>>>(aggbuf, w2r, hbuf, as2, ad2, as, ad, n, 256);
    agg_warp_kernel<<<agg_blocks, 256>>>(hbuf, csr_src, offs, deg, as, ad, b2, aggbuf, n, 1, 0);

    // Layer 3
    gemm3_alpha_kernel<<<cdiv(n * 32, 256), 256>>>(aggbuf, W3, as3, ad3, h3, as, ad, n);
    agg3_fused_kernel<<<cdiv(n, 256), 256>>>(h3, csr_src, offs, deg, as, ad, b3, outp, n);
}

// round 7
// speedup vs baseline: 2.9700x; 1.2021x over previous
#include <cuda_runtime.h>
#include <cuda_fp16.h>
#include <math.h>
#include <limits.h>

#define NMAX 50000
#define EMAX 800000
#define HCMAX 256

// ---------------- scratch ----------------
__device__ __half g_hbuf[NMAX * HCMAX];   // GEMM output h, fp16 (gather-only consumer)
__device__ float g_aggbuf[NMAX * HCMAX];
__device__ float g_xr[NMAX * 128];        // tf32-rounded x
__device__ float g_w1r[128 * 256];        // tf32-rounded W1
__device__ float g_w2r[256 * 256];        // tf32-rounded W2
__device__ float g_h3[NMAX * 2];
__device__ float g_as[NMAX * 4];
__device__ float g_ad[NMAX * 4];
__device__ int   g_deg[NMAX];
__device__ int   g_offs[NMAX];
__device__ int   g_cursor[NMAX];
__device__ int   g_bsum[256];
__device__ int   g_csr_src[EMAX];

static inline int cdiv(int a, int b) { return (a + b - 1) / b; }

__device__ __forceinline__ unsigned f2tf(float x) {
    unsigned u;
    asm("cvt.rna.tf32.f32 %0, %1;" : "=r"(u) : "f"(x));
    return u;
}
__device__ __forceinline__ float roundtf(float x) { return __uint_as_float(f2tf(x)); }

// ---------------- tf32 pre-round (elementwise) ----------------
__global__ void round_tf32_kernel(const float* __restrict__ in, float* __restrict__ out, int n4) {
    int i = blockIdx.x * blockDim.x + threadIdx.x;
    if (i >= n4) return;
    float4 v = ((const float4*)in)[i];
    v.x = roundtf(v.x); v.y = roundtf(v.y); v.z = roundtf(v.z); v.w = roundtf(v.w);
    ((float4*)out)[i] = v;
}

// ---------------- utility ----------------
__global__ void fill_i32(int* p, int v, int n) {
    int i = blockIdx.x * blockDim.x + threadIdx.x;
    if (i < n) p[i] = v;
}

// ---------------- CSR build ----------------
__global__ void hist_kernel(const int* __restrict__ ei, int* __restrict__ deg, int E) {
    int i = blockIdx.x * blockDim.x + threadIdx.x;
    if (i < E) atomicAdd(&deg[ei[E + i]], 1);
}

__global__ void scan_block_kernel(const int* __restrict__ deg, int* __restrict__ offs,
                                  int* __restrict__ bsum, int n) {
    __shared__ int ws[8];
    int t = threadIdx.x, lane = t & 31, w = t >> 5;
    int i = blockIdx.x * 256 + t;
    int v = (i < n) ? deg[i] : 0;
    int x = v;
#pragma unroll
    for (int o = 1; o < 32; o <<= 1) {
        int tv = __shfl_up_sync(0xffffffffu, x, o);
        if (lane >= o) x += tv;
    }
    if (lane == 31) ws[w] = x;
    __syncthreads();
    if (w == 0) {
        int y = (lane < 8) ? ws[lane] : 0;
#pragma unroll
        for (int o = 1; o < 8; o <<= 1) {
            int tv = __shfl_up_sync(0xffffffffu, y, o);
            if (lane >= o) y += tv;
        }
        if (lane < 8) ws[lane] = y;
    }
    __syncthreads();
    int woff = w ? ws[w - 1] : 0;
    if (i < n) offs[i] = woff + x - v;
    if (t == 255) bsum[blockIdx.x] = ws[7];
}

__global__ void scan_sums_kernel(int* bsum, int nb) {
    __shared__ int ws[8];
    int t = threadIdx.x, lane = t & 31, w = t >> 5;
    int v = (t < nb) ? bsum[t] : 0;
    int x = v;
#pragma unroll
    for (int o = 1; o < 32; o <<= 1) {
        int tv = __shfl_up_sync(0xffffffffu, x, o);
        if (lane >= o) x += tv;
    }
    if (lane == 31) ws[w] = x;
    __syncthreads();
    if (w == 0) {
        int y = (lane < 8) ? ws[lane] : 0;
#pragma unroll
        for (int o = 1; o < 8; o <<= 1) {
            int tv = __shfl_up_sync(0xffffffffu, y, o);
            if (lane >= o) y += tv;
        }
        if (lane < 8) ws[lane] = y;
    }
    __syncthreads();
    int woff = w ? ws[w - 1] : 0;
    if (t < nb) bsum[t] = woff + x - v;
}

__global__ void scan_add_kernel(int* __restrict__ offs, int* __restrict__ cursor,
                                const int* __restrict__ bsum, int n) {
    int i = blockIdx.x * blockDim.x + threadIdx.x;
    if (i < n) {
        int o = offs[i] + bsum[blockIdx.x];
        offs[i] = o;
        cursor[i] = o;
    }
}

__global__ void scatter_kernel(const int* __restrict__ ei, int* __restrict__ cursor,
                               int* __restrict__ csr_src, int E) {
    int i = blockIdx.x * blockDim.x + threadIdx.x;
    if (i >= E) return;
    int s = ei[i];
    int d = ei[E + i];
    int p = atomicAdd(&cursor[d], 1);
    csr_src[p] = s;
}

// ---------------- tf32 MMA GEMM, cp.async double-buffered, fp16 C output ----------------
__device__ __forceinline__ void mma_tf32(float* c, const unsigned* a, unsigned b0, unsigned b1) {
    asm volatile(
        "mma.sync.aligned.m16n8k8.row.col.f32.tf32.tf32.f32 "
        "{%0,%1,%2,%3},{%4,%5,%6,%7},{%8,%9},{%0,%1,%2,%3};"
        : "+f"(c[0]), "+f"(c[1]), "+f"(c[2]), "+f"(c[3])
        : "r"(a[0]), "r"(a[1]), "r"(a[2]), "r"(a[3]), "r"(b0), "r"(b1));
}

__device__ __forceinline__ void cpasync16(void* dst_smem, const void* src, bool pred) {
    unsigned d = (unsigned)__cvta_generic_to_shared(dst_smem);
    int sz = pred ? 16 : 0;
    asm volatile("cp.async.cg.shared.global [%0], [%1], 16, %2;\n" :: "r"(d), "l"(src), "r"(sz));
}

#define GBM 128
#define GBN 128
#define GBK 32
#define APITCH (GBK + 4)
#define BPITCH (GBN + 4)
#define ABUF (GBM * APITCH)
#define BBUF (GBK * BPITCH)
#define GEMM_SMEM ((2 * ABUF + 2 * BBUF) * 4)

__global__ __launch_bounds__(256, 2) void mma_gemm_kernel(const float* __restrict__ A,
                                                          const float* __restrict__ B,
                                                          __half* __restrict__ C,
                                                          const float* __restrict__ a_src,
                                                          const float* __restrict__ a_dst,
                                                          float* __restrict__ as_out,
                                                          float* __restrict__ ad_out,
                                                          int M, int K) {
    extern __shared__ float smem[];
    float* sA = smem;
    float* sB = smem + 2 * ABUF;
    int tid = threadIdx.x;
    int bm = blockIdx.x * GBM, bn = blockIdx.y * GBN;
    int lane = tid & 31, wid = tid >> 5;
    int wm = wid >> 1, wn = wid & 1;
    int g = lane >> 2, l4 = lane & 3;

    float acc[2][8][4];
#pragma unroll
    for (int mt = 0; mt < 2; mt++)
#pragma unroll
        for (int nt = 0; nt < 8; nt++)
#pragma unroll
            for (int c = 0; c < 4; c++) acc[mt][nt][c] = 0.f;

    int T = K / GBK;
    int arow = tid >> 3, akq = tid & 7;
    int br = tid >> 5, bc4 = tid & 31;

    {
        float* a0 = sA;
        float* b0 = sB;
#pragma unroll
        for (int i = 0; i < 4; i++) {
            int row = arow + i * 32;
            int gr = bm + row;
            bool p = gr < M;
            int grc = p ? gr : 0;
            cpasync16(&a0[row * APITCH + akq * 4], &A[(size_t)grc * K + akq * 4], p);
            int r = br + i * 8;
            cpasync16(&b0[r * BPITCH + bc4 * 4], &B[(size_t)r * 256 + bn + bc4 * 4], true);
        }
        asm volatile("cp.async.commit_group;\n");
    }

    for (int t = 0; t < T; t++) {
        int cb = t & 1;
        if (t + 1 < T) {
            int k0 = (t + 1) * GBK;
            float* a1 = sA + ((t + 1) & 1) * ABUF;
            float* b1 = sB + ((t + 1) & 1) * BBUF;
#pragma unroll
            for (int i = 0; i < 4; i++) {
                int row = arow + i * 32;
                int gr = bm + row;
                bool p = gr < M;
                int grc = p ? gr : 0;
                cpasync16(&a1[row * APITCH + akq * 4], &A[(size_t)grc * K + k0 + akq * 4], p);
                int r = br + i * 8;
                cpasync16(&b1[r * BPITCH + bc4 * 4], &B[(size_t)(k0 + r) * 256 + bn + bc4 * 4], true);
            }
            asm volatile("cp.async.commit_group;\n");
            asm volatile("cp.async.wait_group 1;\n");
        } else {
            asm volatile("cp.async.wait_group 0;\n");
        }
        __syncthreads();

        const float* Ac = sA + cb * ABUF;
        const float* Bc = sB + cb * BBUF;
#pragma unroll
        for (int ks = 0; ks < 4; ks++) {
            int kb = ks * 8;
            unsigned a[2][4];
#pragma unroll
            for (int mt = 0; mt < 2; mt++) {
                int row = wm * 32 + mt * 16 + g;
                a[mt][0] = __float_as_uint(Ac[row * APITCH + kb + l4]);
                a[mt][1] = __float_as_uint(Ac[(row + 8) * APITCH + kb + l4]);
                a[mt][2] = __float_as_uint(Ac[row * APITCH + kb + l4 + 4]);
                a[mt][3] = __float_as_uint(Ac[(row + 8) * APITCH + kb + l4 + 4]);
            }
#pragma unroll
            for (int nt = 0; nt < 8; nt++) {
                int col = wn * 64 + nt * 8 + g;
                unsigned b0 = __float_as_uint(Bc[(kb + l4) * BPITCH + col]);
                unsigned b1 = __float_as_uint(Bc[(kb + l4 + 4) * BPITCH + col]);
                mma_tf32(acc[0][nt], a[0], b0, b1);
                mma_tf32(acc[1][nt], a[1], b0, b1);
            }
        }
        __syncthreads();
    }

    // C store as fp16 (half2 per (mt,nt) row-pair element)
#pragma unroll
    for (int mt = 0; mt < 2; mt++) {
#pragma unroll
        for (int nt = 0; nt < 8; nt++) {
            int row0 = bm + wm * 32 + mt * 16 + g;
            int col = bn + wn * 64 + nt * 8 + l4 * 2;
            if (row0 < M)
                *(__half2*)&C[(size_t)row0 * 256 + col] = __floats2half2_rn(acc[mt][nt][0], acc[mt][nt][1]);
            if (row0 + 8 < M)
                *(__half2*)&C[(size_t)(row0 + 8) * 256 + col] = __floats2half2_rn(acc[mt][nt][2], acc[mt][nt][3]);
        }
    }

    // fused alpha epilogue from fp32 accumulators
    int head = (bn + wn * 64) >> 6;
    const float* asv = a_src + head * 64;
    const float* adv = a_dst + head * 64;
#pragma unroll
    for (int mt = 0; mt < 2; mt++) {
        float sA_ = 0.f, dA_ = 0.f, sB_ = 0.f, dB_ = 0.f;
#pragma unroll
        for (int nt = 0; nt < 8; nt++) {
            int lc = nt * 8 + l4 * 2;
            float w0 = __ldg(&asv[lc]), w1 = __ldg(&asv[lc + 1]);
            float u0 = __ldg(&adv[lc]), u1 = __ldg(&adv[lc + 1]);
            sA_ += acc[mt][nt][0] * w0 + acc[mt][nt][1] * w1;
            dA_ += acc[mt][nt][0] * u0 + acc[mt][nt][1] * u1;
            sB_ += acc[mt][nt][2] * w0 + acc[mt][nt][3] * w1;
            dB_ += acc[mt][nt][2] * u0 + acc[mt][nt][3] * u1;
        }
#pragma unroll
        for (int o = 1; o < 4; o <<= 1) {
            sA_ += __shfl_xor_sync(0xffffffffu, sA_, o);
            dA_ += __shfl_xor_sync(0xffffffffu, dA_, o);
            sB_ += __shfl_xor_sync(0xffffffffu, sB_, o);
            dB_ += __shfl_xor_sync(0xffffffffu, dB_, o);
        }
        if (l4 == 0) {
            int row0 = bm + wm * 32 + mt * 16 + g;
            if (row0 < M) {
                as_out[row0 * 4 + head] = sA_;
                ad_out[row0 * 4 + head] = dA_;
            }
            if (row0 + 8 < M) {
                as_out[(row0 + 8) * 4 + head] = sB_;
                ad_out[(row0 + 8) * 4 + head] = dB_;
            }
        }
    }
}

__device__ __forceinline__ float lrelu(float v) { return v > 0.f ? v : 0.2f * v; }

// ---------------- warp-per-node aggregation: fp16 h, 8 channels/lane ----------------
__global__ __launch_bounds__(256) void agg_warp_kernel(const __half* __restrict__ h,
                                                       const int* __restrict__ csr_src,
                                                       const int* __restrict__ offs,
                                                       const int* __restrict__ deg,
                                                       const float* __restrict__ as,
                                                       const float* __restrict__ ad,
                                                       const float* __restrict__ bias,
                                                       float* __restrict__ out,
                                                       int n, int do_relu, int do_round) {
    int node = (blockIdx.x * blockDim.x + threadIdx.x) >> 5;
    int lane = threadIdx.x & 31;
    if (node >= n) return;
    int myhead = lane >> 3;      // head owning this lane's 8 channels
    int j = lane & 3;            // head role for e-computation
    int i = lane >> 2;           // edge slot 0..7 for e-computation
    int st = offs[node], d = deg[node];
    float adn = ad[node * 4 + j];

    float m = -1e30f, z = 0.f;
    float4 acc0 = make_float4(0.f, 0.f, 0.f, 0.f);
    float4 acc1 = make_float4(0.f, 0.f, 0.f, 0.f);

    for (int base = 0; base < d; base += 8) {
        int cnt = min(8, d - base);
        int src = (lane < cnt) ? csr_src[st + base + lane] : 0;
        int s_i = __shfl_sync(0xffffffffu, src, i);
        float e = (i < cnt) ? lrelu(as[s_i * 4 + j] + adn) : -1e30f;
        float cm = e;
#pragma unroll
        for (int o = 4; o < 32; o <<= 1) cm = fmaxf(cm, __shfl_xor_sync(0xffffffffu, cm, o));
        float nm = fmaxf(m, cm);
        float p = __expf(e - nm);
        float ps = p;
#pragma unroll
        for (int o = 4; o < 32; o <<= 1) ps += __shfl_xor_sync(0xffffffffu, ps, o);
        float scale = __expf(m - nm);
        z = z * scale + ps;
        m = nm;
        float scale_my = __shfl_sync(0xffffffffu, scale, myhead * 5);
        acc0.x *= scale_my; acc0.y *= scale_my; acc0.z *= scale_my; acc0.w *= scale_my;
        acc1.x *= scale_my; acc1.y *= scale_my; acc1.z *= scale_my; acc1.w *= scale_my;
#pragma unroll 8
        for (int q = 0; q < cnt; q++) {
            int s = __shfl_sync(0xffffffffu, src, q);
            float pq = __shfl_sync(0xffffffffu, p, q * 4 + myhead);
            uint4 hv = *(const uint4*)(h + (size_t)s * 256 + lane * 8);  // 8 halves
            float2 f0 = __half22float2(*(__half2*)&hv.x);
            float2 f1 = __half22float2(*(__half2*)&hv.y);
            float2 f2 = __half22float2(*(__half2*)&hv.z);
            float2 f3 = __half22float2(*(__half2*)&hv.w);
            acc0.x += pq * f0.x; acc0.y += pq * f0.y;
            acc0.z += pq * f1.x; acc0.w += pq * f1.y;
            acc1.x += pq * f2.x; acc1.y += pq * f2.y;
            acc1.z += pq * f3.x; acc1.w += pq * f3.y;
        }
    }
    float z_my = __shfl_sync(0xffffffffu, z, myhead * 5);
    float rz = 1.f / (z_my + 1e-16f);
    const float4* bp = (const float4*)(bias + lane * 8);
    float4 b0 = bp[0], b1 = bp[1];
    float4 o0, o1;
    o0.x = acc0.x * rz + b0.x; o0.y = acc0.y * rz + b0.y;
    o0.z = acc0.z * rz + b0.z; o0.w = acc0.w * rz + b0.w;
    o1.x = acc1.x * rz + b1.x; o1.y = acc1.y * rz + b1.y;
    o1.z = acc1.z * rz + b1.z; o1.w = acc1.w * rz + b1.w;
    if (do_relu) {
        o0.x = fmaxf(o0.x, 0.f); o0.y = fmaxf(o0.y, 0.f);
        o0.z = fmaxf(o0.z, 0.f); o0.w = fmaxf(o0.w, 0.f);
        o1.x = fmaxf(o1.x, 0.f); o1.y = fmaxf(o1.y, 0.f);
        o1.z = fmaxf(o1.z, 0.f); o1.w = fmaxf(o1.w, 0.f);
    }
    if (do_round) {
        o0.x = roundtf(o0.x); o0.y = roundtf(o0.y); o0.z = roundtf(o0.z); o0.w = roundtf(o0.w);
        o1.x = roundtf(o1.x); o1.y = roundtf(o1.y); o1.z = roundtf(o1.z); o1.w = roundtf(o1.w);
    }
    float4* op = (float4*)(out + (size_t)node * 256 + lane * 8);
    op[0] = o0;
    op[1] = o1;
}

// ---------------- layer3: GEMM [N,256]@[256,2] fused with alpha coeffs ----------------
__global__ void gemm3_alpha_kernel(const float* __restrict__ h, const float* __restrict__ W3,
                                   const float* __restrict__ a_s, const float* __restrict__ a_d,
                                   float* __restrict__ h3, float* __restrict__ as,
                                   float* __restrict__ ad, int n) {
    __shared__ float w[512];
    for (int i = threadIdx.x; i < 512; i += blockDim.x) w[i] = W3[i];
    __syncthreads();
    int gt = blockIdx.x * blockDim.x + threadIdx.x;
    int warp = gt >> 5;
    int lane = gt & 31;
    if (warp >= n) return;
    const float* hr = h + (size_t)warp * 256;
    float a0 = 0.f, a1 = 0.f;
#pragma unroll
    for (int k = 0; k < 8; k++) {
        int i = lane + 32 * k;
        float v = hr[i];
        a0 += v * w[i * 2];
        a1 += v * w[i * 2 + 1];
    }
#pragma unroll
    for (int o = 16; o; o >>= 1) {
        a0 += __shfl_xor_sync(0xffffffffu, a0, o);
        a1 += __shfl_xor_sync(0xffffffffu, a1, o);
    }
    if (lane == 0) {
        h3[2 * warp] = a0;
        h3[2 * warp + 1] = a1;
        as[warp] = a0 * a_s[0] + a1 * a_s[1];
        ad[warp] = a0 * a_d[0] + a1 * a_d[1];
    }
}

// ---------------- layer3 fused aggregation (H=1, C=2) ----------------
__global__ void agg3_fused_kernel(const float* __restrict__ h3, const int* __restrict__ csr_src,
                                  const int* __restrict__ offs, const int* __restrict__ deg,
                                  const float* __restrict__ as, const float* __restrict__ ad,
                                  const float* __restrict__ bias, float* __restrict__ out, int n) {
    int i = blockIdx.x * blockDim.x + threadIdx.x;
    if (i >= n) return;
    int st = offs[i], d = deg[i];
    float adn = ad[i];
    float mt = -1e30f, zt = 0.f;
    float a0 = 0.f, a1 = 0.f;
    for (int k = 0; k < d; k++) {
        int s = csr_src[st + k];
        float e = lrelu(as[s] + adn);
        float nm = fmaxf(mt, e);
        float scale = __expf(mt - nm);
        float p = __expf(e - nm);
        zt = zt * scale + p;
        a0 = a0 * scale + p * h3[2 * s];
        a1 = a1 * scale + p * h3[2 * s + 1];
        mt = nm;
    }
    float rz = 1.f / (zt + 1e-16f);
    out[2 * i] = a0 * rz + bias[0];
    out[2 * i + 1] = a1 * rz + bias[1];
}

// ---------------- launcher ----------------
extern "C" void kernel_launch(void* const* d_in, const int* in_sizes, int n_in,
                              void* d_out, int out_size) {
    const float* x   = (const float*)d_in[0];
    const int*   ei  = (const int*)d_in[1];
    const float* W1  = (const float*)d_in[2];
    const float* as1 = (const float*)d_in[3];
    const float* ad1 = (const float*)d_in[4];
    const float* b1  = (const float*)d_in[5];
    const float* W2  = (const float*)d_in[6];
    const float* as2 = (const float*)d_in[7];
    const float* ad2 = (const float*)d_in[8];
    const float* b2  = (const float*)d_in[9];
    const float* W3  = (const float*)d_in[10];
    const float* as3 = (const float*)d_in[11];
    const float* ad3 = (const float*)d_in[12];
    const float* b3  = (const float*)d_in[13];
    float* outp = (float*)d_out;

    int n = in_sizes[0] / 128;
    int E = in_sizes[1] / 2;

    __half* hbuf;
    float *aggbuf, *xr, *w1r, *w2r, *h3, *as, *ad;
    int *deg, *offs, *cursor, *bsum, *csr_src;
    cudaGetSymbolAddress((void**)&hbuf, g_hbuf);
    cudaGetSymbolAddress((void**)&aggbuf, g_aggbuf);
    cudaGetSymbolAddress((void**)&xr, g_xr);
    cudaGetSymbolAddress((void**)&w1r, g_w1r);
    cudaGetSymbolAddress((void**)&w2r, g_w2r);
    cudaGetSymbolAddress((void**)&h3, g_h3);
    cudaGetSymbolAddress((void**)&as, g_as);
    cudaGetSymbolAddress((void**)&ad, g_ad);
    cudaGetSymbolAddress((void**)&deg, g_deg);
    cudaGetSymbolAddress((void**)&offs, g_offs);
    cudaGetSymbolAddress((void**)&cursor, g_cursor);
    cudaGetSymbolAddress((void**)&bsum, g_bsum);
    cudaGetSymbolAddress((void**)&csr_src, g_csr_src);

    cudaFuncSetAttribute(mma_gemm_kernel, cudaFuncAttributeMaxDynamicSharedMemorySize, GEMM_SMEM);

    int nb = cdiv(n, 256);
    dim3 gemm_grid(cdiv(n, 128), 2);
    int agg_blocks = cdiv(n * 32, 256);

    // pre-round inputs to tf32-representable fp32
    round_tf32_kernel<<<cdiv(n * 128 / 4, 256), 256>>>(x, xr, n * 128 / 4);       // 0
    round_tf32_kernel<<<cdiv(128 * 256 / 4, 256), 256>>>(W1, w1r, 128 * 256 / 4); // 1
    round_tf32_kernel<<<cdiv(256 * 256 / 4, 256), 256>>>(W2, w2r, 256 * 256 / 4); // 2

    // GEMM1 at launch idx 3 (profiled)
    mma_gemm_kernel<<<gemm_grid, 256, GEMM_SMEM>>>(xr, w1r, hbuf, as1, ad1, as, ad, n, 128); // 3

    // CSR build
    fill_i32<<<cdiv(n, 256), 256>>>(deg, 0, n);                       // 4
    hist_kernel<<<cdiv(E, 256), 256>>>(ei, deg, E);                   // 5
    scan_block_kernel<<<nb, 256>>>(deg, offs, bsum, n);               // 6
    scan_sums_kernel<<<1, 256>>>(bsum, nb);                           // 7
    scan_add_kernel<<<nb, 256>>>(offs, cursor, bsum, n);              // 8
    scatter_kernel<<<cdiv(E, 256), 256>>>(ei, cursor, csr_src, E);    // 9

    // Layer 1 aggregation (round output: GEMM2's A operand)
    agg_warp_kernel<<<agg_blocks, 256>>>(hbuf, csr_src, offs, deg, as, ad, b1, aggbuf, n, 1, 1);

    // Layer 2
    mma_gemm_kernel<<<gemm_grid, 256, GEMM_SMEM>>>(aggbuf, w2r, hbuf, as2, ad2, as, ad, n, 256);
    agg_warp_kernel<<<agg_blocks, 256>>>(hbuf, csr_src, offs, deg, as, ad, b2, aggbuf, n, 1, 0);

    // Layer 3
    gemm3_alpha_kernel<<<cdiv(n * 32, 256), 256>>>(aggbuf, W3, as3, ad3, h3, as, ad, n);
    agg3_fused_kernel<<<cdiv(n, 256), 256>>>(h3, csr_src, offs, deg, as, ad, b3, outp, n);
}

// round 8
// speedup vs baseline: 3.6294x; 1.2220x over previous
#include <cuda_runtime.h>
#include <cuda_fp16.h>
#include <math.h>
#include <limits.h>

#define NMAX 50000
#define EMAX 800000
#define HCMAX 256

// ---------------- scratch ----------------
__device__ __half g_hbuf[NMAX * HCMAX];   // GEMM output h (gather-only consumer)
__device__ __half g_aggbuf[NMAX * HCMAX]; // agg output (= next GEMM's A operand)
__device__ __half g_xh[NMAX * 128];       // fp16 x
__device__ __half g_w1h[128 * 256];       // fp16 W1
__device__ __half g_w2h[256 * 256];       // fp16 W2
__device__ float g_h3[NMAX * 2];
__device__ float g_as[NMAX * 4];
__device__ float g_ad[NMAX * 4];
__device__ int   g_deg[NMAX];
__device__ int   g_offs[NMAX];
__device__ int   g_cursor[NMAX];
__device__ int   g_bsum[256];
__device__ int   g_csr_src[EMAX];

static inline int cdiv(int a, int b) { return (a + b - 1) / b; }

// ---------------- fp32 -> fp16 convert ----------------
__global__ void f32_to_f16_kernel(const float* __restrict__ in, __half* __restrict__ out, int n4) {
    int i = blockIdx.x * blockDim.x + threadIdx.x;
    if (i >= n4) return;
    float4 v = ((const float4*)in)[i];
    __half2 h0 = __floats2half2_rn(v.x, v.y);
    __half2 h1 = __floats2half2_rn(v.z, v.w);
    ((__half2*)out)[i * 2] = h0;
    ((__half2*)out)[i * 2 + 1] = h1;
}

// ---------------- utility ----------------
__global__ void fill_i32(int* p, int v, int n) {
    int i = blockIdx.x * blockDim.x + threadIdx.x;
    if (i < n) p[i] = v;
}

// ---------------- CSR build ----------------
__global__ void hist_kernel(const int* __restrict__ ei, int* __restrict__ deg, int E) {
    int i = blockIdx.x * blockDim.x + threadIdx.x;
    if (i < E) atomicAdd(&deg[ei[E + i]], 1);
}

__global__ void scan_block_kernel(const int* __restrict__ deg, int* __restrict__ offs,
                                  int* __restrict__ bsum, int n) {
    __shared__ int ws[8];
    int t = threadIdx.x, lane = t & 31, w = t >> 5;
    int i = blockIdx.x * 256 + t;
    int v = (i < n) ? deg[i] : 0;
    int x = v;
#pragma unroll
    for (int o = 1; o < 32; o <<= 1) {
        int tv = __shfl_up_sync(0xffffffffu, x, o);
        if (lane >= o) x += tv;
    }
    if (lane == 31) ws[w] = x;
    __syncthreads();
    if (w == 0) {
        int y = (lane < 8) ? ws[lane] : 0;
#pragma unroll
        for (int o = 1; o < 8; o <<= 1) {
            int tv = __shfl_up_sync(0xffffffffu, y, o);
            if (lane >= o) y += tv;
        }
        if (lane < 8) ws[lane] = y;
    }
    __syncthreads();
    int woff = w ? ws[w - 1] : 0;
    if (i < n) offs[i] = woff + x - v;
    if (t == 255) bsum[blockIdx.x] = ws[7];
}

__global__ void scan_sums_kernel(int* bsum, int nb) {
    __shared__ int ws[8];
    int t = threadIdx.x, lane = t & 31, w = t >> 5;
    int v = (t < nb) ? bsum[t] : 0;
    int x = v;
#pragma unroll
    for (int o = 1; o < 32; o <<= 1) {
        int tv = __shfl_up_sync(0xffffffffu, x, o);
        if (lane >= o) x += tv;
    }
    if (lane == 31) ws[w] = x;
    __syncthreads();
    if (w == 0) {
        int y = (lane < 8) ? ws[lane] : 0;
#pragma unroll
        for (int o = 1; o < 8; o <<= 1) {
            int tv = __shfl_up_sync(0xffffffffu, y, o);
            if (lane >= o) y += tv;
        }
        if (lane < 8) ws[lane] = y;
    }
    __syncthreads();
    int woff = w ? ws[w - 1] : 0;
    if (t < nb) bsum[t] = woff + x - v;
}

__global__ void scan_add_kernel(int* __restrict__ offs, int* __restrict__ cursor,
                                const int* __restrict__ bsum, int n) {
    int i = blockIdx.x * blockDim.x + threadIdx.x;
    if (i < n) {
        int o = offs[i] + bsum[blockIdx.x];
        offs[i] = o;
        cursor[i] = o;
    }
}

__global__ void scatter_kernel(const int* __restrict__ ei, int* __restrict__ cursor,
                               int* __restrict__ csr_src, int E) {
    int i = blockIdx.x * blockDim.x + threadIdx.x;
    if (i >= E) return;
    int s = ei[i];
    int d = ei[E + i];
    int p = atomicAdd(&cursor[d], 1);
    csr_src[p] = s;
}

// ---------------- fp16 MMA GEMM (m16n8k16, fp32 accum), ldmatrix, cp.async ----------------
__device__ __forceinline__ void mma_f16(float* c, const unsigned* a, unsigned b0, unsigned b1) {
    asm volatile(
        "mma.sync.aligned.m16n8k16.row.col.f32.f16.f16.f32 "
        "{%0,%1,%2,%3},{%4,%5,%6,%7},{%8,%9},{%0,%1,%2,%3};"
        : "+f"(c[0]), "+f"(c[1]), "+f"(c[2]), "+f"(c[3])
        : "r"(a[0]), "r"(a[1]), "r"(a[2]), "r"(a[3]), "r"(b0), "r"(b1));
}

__device__ __forceinline__ void ldsm_x4(unsigned& r0, unsigned& r1, unsigned& r2, unsigned& r3,
                                        unsigned addr) {
    asm volatile("ldmatrix.sync.aligned.m8n8.x4.shared.b16 {%0,%1,%2,%3}, [%4];"
                 : "=r"(r0), "=r"(r1), "=r"(r2), "=r"(r3) : "r"(addr));
}

__device__ __forceinline__ void ldsm_x4t(unsigned& r0, unsigned& r1, unsigned& r2, unsigned& r3,
                                         unsigned addr) {
    asm volatile("ldmatrix.sync.aligned.m8n8.x4.trans.shared.b16 {%0,%1,%2,%3}, [%4];"
                 : "=r"(r0), "=r"(r1), "=r"(r2), "=r"(r3) : "r"(addr));
}

__device__ __forceinline__ void cpasync16(void* dst_smem, const void* src, bool pred) {
    unsigned d = (unsigned)__cvta_generic_to_shared(dst_smem);
    int sz = pred ? 16 : 0;
    asm volatile("cp.async.cg.shared.global [%0], [%1], 16, %2;\n" :: "r"(d), "l"(src), "r"(sz));
}

#define GBM 128
#define GBN 128
#define GBK 32
#define APITCH 40          // halves per A row (80B, ldmatrix conflict-free)
#define BPITCH 136         // halves per B row (272B, ldmatrix conflict-free)
#define ABUF (GBM * APITCH)
#define BBUF (GBK * BPITCH)
#define GEMM_SMEM ((2 * ABUF + 2 * BBUF) * 2)

__global__ __launch_bounds__(256, 2) void mma_gemm_kernel(const __half* __restrict__ A,
                                                          const __half* __restrict__ B,
                                                          __half* __restrict__ C,
                                                          const float* __restrict__ a_src,
                                                          const float* __restrict__ a_dst,
                                                          float* __restrict__ as_out,
                                                          float* __restrict__ ad_out,
                                                          int M, int K) {
    extern __shared__ __half smem[];
    __half* sA = smem;               // 2 x ABUF halves
    __half* sB = smem + 2 * ABUF;    // 2 x BBUF halves
    int tid = threadIdx.x;
    int bm = blockIdx.x * GBM, bn = blockIdx.y * GBN;
    int lane = tid & 31, wid = tid >> 5;
    int wm = wid >> 1, wn = wid & 1;
    int g = lane >> 2, l4 = lane & 3;

    float acc[2][8][4];
#pragma unroll
    for (int mt = 0; mt < 2; mt++)
#pragma unroll
        for (int nt = 0; nt < 8; nt++)
#pragma unroll
            for (int c = 0; c < 4; c++) acc[mt][nt][c] = 0.f;

    int T = K / GBK;
    // A: 128 rows x 32 halves = 512 x 16B chunks (2/thread): idx -> row=idx>>2, kc=idx&3
    // B: 32 rows x 128 halves = 512 chunks: idx -> r=idx>>4, c=idx&15
    unsigned sAu = (unsigned)__cvta_generic_to_shared(sA);
    unsigned sBu = (unsigned)__cvta_generic_to_shared(sB);

    // ldmatrix source offsets (in halves, relative to buffer base)
    int lrow = (lane & 7) + ((lane >> 3) & 1) * 8;
    int lcol8 = (lane >> 4) * 8;

#define LOAD_TILE(buf, k0)                                                              \
    {                                                                                   \
        __half* a_ = sA + (buf) * ABUF;                                                 \
        __half* b_ = sB + (buf) * BBUF;                                                 \
        _Pragma("unroll")                                                               \
        for (int i = 0; i < 2; i++) {                                                   \
            int idx = tid + i * 256;                                                    \
            int row = idx >> 2, kc = idx & 3;                                           \
            int gr = bm + row;                                                          \
            bool p = gr < M;                                                            \
            int grc = p ? gr : 0;                                                       \
            cpasync16(&a_[row * APITCH + kc * 8], &A[(size_t)grc * K + (k0) + kc * 8], p); \
            int r = idx >> 4, c = idx & 15;                                             \
            cpasync16(&b_[r * BPITCH + c * 8], &B[(size_t)((k0) + r) * 256 + bn + c * 8], true); \
        }                                                                               \
        asm volatile("cp.async.commit_group;\n");                                       \
    }

    LOAD_TILE(0, 0)

    for (int t = 0; t < T; t++) {
        int cb = t & 1;
        if (t + 1 < T) {
            LOAD_TILE((t + 1) & 1, (t + 1) * GBK)
            asm volatile("cp.async.wait_group 1;\n");
        } else {
            asm volatile("cp.async.wait_group 0;\n");
        }
        __syncthreads();

        unsigned aBase = sAu + cb * ABUF * 2;
        unsigned bBase = sBu + cb * BBUF * 2;
#pragma unroll
        for (int ks = 0; ks < 2; ks++) {
            int kb = ks * 16;
            unsigned a[2][4];
#pragma unroll
            for (int mt = 0; mt < 2; mt++) {
                int row = wm * 32 + mt * 16 + lrow;
                ldsm_x4(a[mt][0], a[mt][1], a[mt][2], a[mt][3],
                        aBase + (row * APITCH + kb + lcol8) * 2);
            }
#pragma unroll
            for (int nt2 = 0; nt2 < 4; nt2++) {
                int n0 = wn * 64 + nt2 * 16;
                unsigned b0, b1, b2, b3;
                ldsm_x4t(b0, b1, b2, b3, bBase + ((kb + lrow) * BPITCH + n0 + lcol8) * 2);
                mma_f16(acc[0][nt2 * 2], a[0], b0, b1);
                mma_f16(acc[1][nt2 * 2], a[1], b0, b1);
                mma_f16(acc[0][nt2 * 2 + 1], a[0], b2, b3);
                mma_f16(acc[1][nt2 * 2 + 1], a[1], b2, b3);
            }
        }
        __syncthreads();
    }

    // C store (fp16)
#pragma unroll
    for (int mt = 0; mt < 2; mt++) {
#pragma unroll
        for (int nt = 0; nt < 8; nt++) {
            int row0 = bm + wm * 32 + mt * 16 + g;
            int col = bn + wn * 64 + nt * 8 + l4 * 2;
            if (row0 < M)
                *(__half2*)&C[(size_t)row0 * 256 + col] = __floats2half2_rn(acc[mt][nt][0], acc[mt][nt][1]);
            if (row0 + 8 < M)
                *(__half2*)&C[(size_t)(row0 + 8) * 256 + col] = __floats2half2_rn(acc[mt][nt][2], acc[mt][nt][3]);
        }
    }

    // fused alpha epilogue from fp32 accumulators
    int head = (bn + wn * 64) >> 6;
    const float* asv = a_src + head * 64;
    const float* adv = a_dst + head * 64;
#pragma unroll
    for (int mt = 0; mt < 2; mt++) {
        float sA_ = 0.f, dA_ = 0.f, sB_ = 0.f, dB_ = 0.f;
#pragma unroll
        for (int nt = 0; nt < 8; nt++) {
            int lc = nt * 8 + l4 * 2;
            float w0 = __ldg(&asv[lc]), w1 = __ldg(&asv[lc + 1]);
            float u0 = __ldg(&adv[lc]), u1 = __ldg(&adv[lc + 1]);
            sA_ += acc[mt][nt][0] * w0 + acc[mt][nt][1] * w1;
            dA_ += acc[mt][nt][0] * u0 + acc[mt][nt][1] * u1;
            sB_ += acc[mt][nt][2] * w0 + acc[mt][nt][3] * w1;
            dB_ += acc[mt][nt][2] * u0 + acc[mt][nt][3] * u1;
        }
#pragma unroll
        for (int o = 1; o < 4; o <<= 1) {
            sA_ += __shfl_xor_sync(0xffffffffu, sA_, o);
            dA_ += __shfl_xor_sync(0xffffffffu, dA_, o);
            sB_ += __shfl_xor_sync(0xffffffffu, sB_, o);
            dB_ += __shfl_xor_sync(0xffffffffu, dB_, o);
        }
        if (l4 == 0) {
            int row0 = bm + wm * 32 + mt * 16 + g;
            if (row0 < M) {
                as_out[row0 * 4 + head] = sA_;
                ad_out[row0 * 4 + head] = dA_;
            }
            if (row0 + 8 < M) {
                as_out[(row0 + 8) * 4 + head] = sB_;
                ad_out[(row0 + 8) * 4 + head] = dB_;
            }
        }
    }
}

__device__ __forceinline__ float lrelu(float v) { return v > 0.f ? v : 0.2f * v; }

// ---------------- warp-per-node aggregation: fp16 in, fp16 out ----------------
__global__ __launch_bounds__(256) void agg_warp_kernel(const __half* __restrict__ h,
                                                       const int* __restrict__ csr_src,
                                                       const int* __restrict__ offs,
                                                       const int* __restrict__ deg,
                                                       const float* __restrict__ as,
                                                       const float* __restrict__ ad,
                                                       const float* __restrict__ bias,
                                                       __half* __restrict__ out,
                                                       int n, int do_relu) {
    int node = (blockIdx.x * blockDim.x + threadIdx.x) >> 5;
    int lane = threadIdx.x & 31;
    if (node >= n) return;
    int myhead = lane >> 3;
    int j = lane & 3;
    int i = lane >> 2;
    int st = offs[node], d = deg[node];
    float adn = ad[node * 4 + j];

    float m = -1e30f, z = 0.f;
    float4 acc0 = make_float4(0.f, 0.f, 0.f, 0.f);
    float4 acc1 = make_float4(0.f, 0.f, 0.f, 0.f);

    for (int base = 0; base < d; base += 8) {
        int cnt = min(8, d - base);
        int src = (lane < cnt) ? csr_src[st + base + lane] : 0;
        int s_i = __shfl_sync(0xffffffffu, src, i);
        float e = (i < cnt) ? lrelu(as[s_i * 4 + j] + adn) : -1e30f;
        float cm = e;
#pragma unroll
        for (int o = 4; o < 32; o <<= 1) cm = fmaxf(cm, __shfl_xor_sync(0xffffffffu, cm, o));
        float nm = fmaxf(m, cm);
        float p = __expf(e - nm);
        float ps = p;
#pragma unroll
        for (int o = 4; o < 32; o <<= 1) ps += __shfl_xor_sync(0xffffffffu, ps, o);
        float scale = __expf(m - nm);
        z = z * scale + ps;
        m = nm;
        float scale_my = __shfl_sync(0xffffffffu, scale, myhead * 5);
        acc0.x *= scale_my; acc0.y *= scale_my; acc0.z *= scale_my; acc0.w *= scale_my;
        acc1.x *= scale_my; acc1.y *= scale_my; acc1.z *= scale_my; acc1.w *= scale_my;
#pragma unroll 8
        for (int q = 0; q < cnt; q++) {
            int s = __shfl_sync(0xffffffffu, src, q);
            float pq = __shfl_sync(0xffffffffu, p, q * 4 + myhead);
            uint4 hv = *(const uint4*)(h + (size_t)s * 256 + lane * 8);
            float2 f0 = __half22float2(*(__half2*)&hv.x);
            float2 f1 = __half22float2(*(__half2*)&hv.y);
            float2 f2 = __half22float2(*(__half2*)&hv.z);
            float2 f3 = __half22float2(*(__half2*)&hv.w);
            acc0.x += pq * f0.x; acc0.y += pq * f0.y;
            acc0.z += pq * f1.x; acc0.w += pq * f1.y;
            acc1.x += pq * f2.x; acc1.y += pq * f2.y;
            acc1.z += pq * f3.x; acc1.w += pq * f3.y;
        }
    }
    float z_my = __shfl_sync(0xffffffffu, z, myhead * 5);
    float rz = 1.f / (z_my + 1e-16f);
    const float4* bp = (const float4*)(bias + lane * 8);
    float4 b0 = bp[0], b1 = bp[1];
    float4 o0, o1;
    o0.x = acc0.x * rz + b0.x; o0.y = acc0.y * rz + b0.y;
    o0.z = acc0.z * rz + b0.z; o0.w = acc0.w * rz + b0.w;
    o1.x = acc1.x * rz + b1.x; o1.y = acc1.y * rz + b1.y;
    o1.z = acc1.z * rz + b1.z; o1.w = acc1.w * rz + b1.w;
    if (do_relu) {
        o0.x = fmaxf(o0.x, 0.f); o0.y = fmaxf(o0.y, 0.f);
        o0.z = fmaxf(o0.z, 0.f); o0.w = fmaxf(o0.w, 0.f);
        o1.x = fmaxf(o1.x, 0.f); o1.y = fmaxf(o1.y, 0.f);
        o1.z = fmaxf(o1.z, 0.f); o1.w = fmaxf(o1.w, 0.f);
    }
    uint4 pk;
    *(__half2*)&pk.x = __floats2half2_rn(o0.x, o0.y);
    *(__half2*)&pk.y = __floats2half2_rn(o0.z, o0.w);
    *(__half2*)&pk.z = __floats2half2_rn(o1.x, o1.y);
    *(__half2*)&pk.w = __floats2half2_rn(o1.z, o1.w);
    *(uint4*)(out + (size_t)node * 256 + lane * 8) = pk;
}

// ---------------- layer3: GEMM [N,256]@[256,2] fused with alpha coeffs ----------------
__global__ void gemm3_alpha_kernel(const __half* __restrict__ h, const float* __restrict__ W3,
                                   const float* __restrict__ a_s, const float* __restrict__ a_d,
                                   float* __restrict__ h3, float* __restrict__ as,
                                   float* __restrict__ ad, int n) {
    __shared__ float w[512];
    for (int i = threadIdx.x; i < 512; i += blockDim.x) w[i] = W3[i];
    __syncthreads();
    int gt = blockIdx.x * blockDim.x + threadIdx.x;
    int warp = gt >> 5;
    int lane = gt & 31;
    if (warp >= n) return;
    const __half2* hr = (const __half2*)(h + (size_t)warp * 256);
    float a0 = 0.f, a1 = 0.f;
#pragma unroll
    for (int k = 0; k < 4; k++) {
        int i = lane + 32 * k;             // half2 index: channels 2i, 2i+1
        float2 f = __half22float2(hr[i]);
        int c = 2 * i;
        a0 += f.x * w[2 * c] + f.y * w[2 * c + 2];
        a1 += f.x * w[2 * c + 1] + f.y * w[2 * c + 3];
    }
#pragma unroll
    for (int o = 16; o; o >>= 1) {
        a0 += __shfl_xor_sync(0xffffffffu, a0, o);
        a1 += __shfl_xor_sync(0xffffffffu, a1, o);
    }
    if (lane == 0) {
        h3[2 * warp] = a0;
        h3[2 * warp + 1] = a1;
        as[warp] = a0 * a_s[0] + a1 * a_s[1];
        ad[warp] = a0 * a_d[0] + a1 * a_d[1];
    }
}

// ---------------- layer3 fused aggregation (H=1, C=2) ----------------
__global__ void agg3_fused_kernel(const float* __restrict__ h3, const int* __restrict__ csr_src,
                                  const int* __restrict__ offs, const int* __restrict__ deg,
                                  const float* __restrict__ as, const float* __restrict__ ad,
                                  const float* __restrict__ bias, float* __restrict__ out, int n) {
    int i = blockIdx.x * blockDim.x + threadIdx.x;
    if (i >= n) return;
    int st = offs[i], d = deg[i];
    float adn = ad[i];
    float mt = -1e30f, zt = 0.f;
    float a0 = 0.f, a1 = 0.f;
    for (int k = 0; k < d; k++) {
        int s = csr_src[st + k];
        float e = lrelu(as[s] + adn);
        float nm = fmaxf(mt, e);
        float scale = __expf(mt - nm);
        float p = __expf(e - nm);
        zt = zt * scale + p;
        a0 = a0 * scale + p * h3[2 * s];
        a1 = a1 * scale + p * h3[2 * s + 1];
        mt = nm;
    }
    float rz = 1.f / (zt + 1e-16f);
    out[2 * i] = a0 * rz + bias[0];
    out[2 * i + 1] = a1 * rz + bias[1];
}

// ---------------- launcher ----------------
extern "C" void kernel_launch(void* const* d_in, const int* in_sizes, int n_in,
                              void* d_out, int out_size) {
    const float* x   = (const float*)d_in[0];
    const int*   ei  = (const int*)d_in[1];
    const float* W1  = (const float*)d_in[2];
    const float* as1 = (const float*)d_in[3];
    const float* ad1 = (const float*)d_in[4];
    const float* b1  = (const float*)d_in[5];
    const float* W2  = (const float*)d_in[6];
    const float* as2 = (const float*)d_in[7];
    const float* ad2 = (const float*)d_in[8];
    const float* b2  = (const float*)d_in[9];
    const float* W3  = (const float*)d_in[10];
    const float* as3 = (const float*)d_in[11];
    const float* ad3 = (const float*)d_in[12];
    const float* b3  = (const float*)d_in[13];
    float* outp = (float*)d_out;

    int n = in_sizes[0] / 128;
    int E = in_sizes[1] / 2;

    __half *hbuf, *aggbuf, *xh, *w1h, *w2h;
    float *h3, *as, *ad;
    int *deg, *offs, *cursor, *bsum, *csr_src;
    cudaGetSymbolAddress((void**)&hbuf, g_hbuf);
    cudaGetSymbolAddress((void**)&aggbuf, g_aggbuf);
    cudaGetSymbolAddress((void**)&xh, g_xh);
    cudaGetSymbolAddress((void**)&w1h, g_w1h);
    cudaGetSymbolAddress((void**)&w2h, g_w2h);
    cudaGetSymbolAddress((void**)&h3, g_h3);
    cudaGetSymbolAddress((void**)&as, g_as);
    cudaGetSymbolAddress((void**)&ad, g_ad);
    cudaGetSymbolAddress((void**)&deg, g_deg);
    cudaGetSymbolAddress((void**)&offs, g_offs);
    cudaGetSymbolAddress((void**)&cursor, g_cursor);
    cudaGetSymbolAddress((void**)&bsum, g_bsum);
    cudaGetSymbolAddress((void**)&csr_src, g_csr_src);

    cudaFuncSetAttribute(mma_gemm_kernel, cudaFuncAttributeMaxDynamicSharedMemorySize, GEMM_SMEM);

    int nb = cdiv(n, 256);
    dim3 gemm_grid(cdiv(n, 128), 2);
    int agg_blocks = cdiv(n * 32, 256);

    // fp32 -> fp16 converts
    f32_to_f16_kernel<<<cdiv(n * 128 / 4, 256), 256>>>(x, xh, n * 128 / 4);        // 0
    f32_to_f16_kernel<<<cdiv(128 * 256 / 4, 256), 256>>>(W1, w1h, 128 * 256 / 4);  // 1
    f32_to_f16_kernel<<<cdiv(256 * 256 / 4, 256), 256>>>(W2, w2h, 256 * 256 / 4);  // 2

    // GEMM1 at launch idx 3 (profiled)
    mma_gemm_kernel<<<gemm_grid, 256, GEMM_SMEM>>>(xh, w1h, hbuf, as1, ad1, as, ad, n, 128); // 3

    // CSR build
    fill_i32<<<cdiv(n, 256), 256>>>(deg, 0, n);                       // 4
    hist_kernel<<<cdiv(E, 256), 256>>>(ei, deg, E);                   // 5
    scan_block_kernel<<<nb, 256>>>(deg, offs, bsum, n);               // 6
    scan_sums_kernel<<<1, 256>>>(bsum, nb);                           // 7
    scan_add_kernel<<<nb, 256>>>(offs, cursor, bsum, n);              // 8
    scatter_kernel<<<cdiv(E, 256), 256>>>(ei, cursor, csr_src, E);    // 9

    // Layer 1 aggregation (fp16 out = GEMM2's A)
    agg_warp_kernel<<<agg_blocks, 256>>>(hbuf, csr_src, offs, deg, as, ad, b1, aggbuf, n, 1);

    // Layer 2
    mma_gemm_kernel<<<gemm_grid, 256, GEMM_SMEM>>>(aggbuf, w2h, hbuf, as2, ad2, as, ad, n, 256);
    agg_warp_kernel<<<agg_blocks, 256>>>(hbuf, csr_src, offs, deg, as, ad, b2, aggbuf, n, 1);

    // Layer 3
    gemm3_alpha_kernel<<<cdiv(n * 32, 256), 256>>>(aggbuf, W3, as3, ad3, h3, as, ad, n);
    agg3_fused_kernel<<<cdiv(n, 256), 256>>>(h3, csr_src, offs, deg, as, ad, b3, outp, n);
}